// round 15
// baseline (speedup 1.0000x reference)
#include <cuda_runtime.h>
#include <cuda_bf16.h>
#include <math.h>
#include <stdint.h>

// Problem constants
#define Bb 32
#define Ll 128
#define Ss 96
#define Ee 768
#define Hh 300
#define Rr 41
#define NPOS 50
#define NLAB 3
#define NG 3        // relation groups (14,14,13)
#define OCW 100
#define SQ 24       // s-rows per sap block

// packed layouts
#define XKW 160
#define WNP 312
#define KW  36
#define TW  52
#define HCH 5408
#define ABUF2 (192*KW + 104*KW)   // 10656 words
#define TBUF  (64*KW + 104*KW)    // 6048 words
#define UBUF  (192*KW + 48*KW)    // 8640 words
#define BBUF 10400

// Scratch (device globals — no allocations allowed)
__device__ float    g_hcmean[Bb*Hh];
__device__ float    g_T[NPOS*Hh];
__device__ float    g_x0[Bb*Ss*Hh];
__device__ float    g_rlen[Bb];
__device__ float    g_vpart[2*Rr*10*Hh];
__device__ float    g_u[Bb*Rr*Ss];
__device__ float    g_part[(size_t)Bb*NG*Ss*Hh];
__device__ int      g_tag64;
__device__ int      g_mask64;
__device__ unsigned short g_perm[Bb][96];
__device__ unsigned short g_segs[Bb][65];
__device__ uint32_t g_xbf[Bb*Ss*XKW];
__device__ uint32_t g_tbf[64*XKW];
__device__ unsigned short g_tht[(size_t)Rr*WNP*64];
__device__ uint32_t g_vbf[2*48*XKW];
__device__ uint32_t g_wbf[(size_t)2*Rr*WNP*XKW];
__device__ uint32_t g_hid[(size_t)Rr*Bb*3*HCH];
__device__ uint32_t g_apbf[(size_t)Bb*Rr*Ss*48];
__device__ uint32_t g_acbf[(size_t)Bb*Rr*Ss*32];

__device__ __forceinline__ uint32_t packbf(float lo, float hi) {
    uint32_t d;
    asm("cvt.rn.bf16x2.f32 %0, %1, %2;" : "=r"(d) : "f"(hi), "f"(lo));
    return d;
}

__device__ __forceinline__ int load_tag(const void* tags, int idx) {
    int t;
    if (g_tag64) t = (int)((const long long*)tags)[idx];
    else         t = ((const int*)tags)[idx];
    return (t < 0) ? 0 : (t >= NPOS ? NPOS-1 : t);
}

__device__ __forceinline__ void cpa16(uint32_t dst_sh, const void* src) {
    asm volatile("cp.async.ca.shared.global [%0], [%1], 16;" :: "r"(dst_sh), "l"(src));
}
#define CP_COMMIT() asm volatile("cp.async.commit_group;")
#define CP_WAIT(n)  asm volatile("cp.async.wait_group %0;" :: "n"(n))

#define MMA_BF16(c, a0,a1,a2,a3, b0,b1) \
    asm volatile("mma.sync.aligned.m16n8k16.row.col.f32.bf16.bf16.f32 " \
        "{%0,%1,%2,%3}, {%4,%5,%6,%7}, {%8,%9}, {%0,%1,%2,%3};" \
        : "+f"((c)[0]), "+f"((c)[1]), "+f"((c)[2]), "+f"((c)[3]) \
        : "r"(a0), "r"(a1), "r"(a2), "r"(a3), "r"(b0), "r"(b1))

#define LDSM4(r0,r1,r2,r3, addr) \
    asm volatile("ldmatrix.sync.aligned.m8n8.x4.shared.b16 {%0,%1,%2,%3}, [%4];" \
        : "=r"(r0), "=r"(r1), "=r"(r2), "=r"(r3) : "r"(addr))

#define LDSM2(r0,r1, addr) \
    asm volatile("ldmatrix.sync.aligned.m8n8.x2.shared.b16 {%0,%1}, [%2];" \
        : "=r"(r0), "=r"(r1) : "r"(addr))

// ---------------------------------------------------------------------------
__device__ void d_detpost(const float* __restrict__ posemb,
                          const float* __restrict__ linW,
                          const float* __restrict__ linb,
                          const float* __restrict__ text,
                          const void* tags, const void* masks,
                          int ntag, int nmask, int bid) {
    int tid = threadIdx.x;  // 320
    if (bid < NPOS) {
        int p = bid;
        __shared__ float pe[Ee];
        for (int e = tid; e < Ee; e += 320) pe[e] = posemb[p*Ee + e];
        __syncthreads();
        if (tid < Hh) {
            float s0=0.f, s1=0.f, s2=0.f, s3=0.f;
            #pragma unroll 2
            for (int e = 0; e < Ee; e += 4) {
                s0 += pe[e  ]*linW[(e  )*Hh + tid];
                s1 += pe[e+1]*linW[(e+1)*Hh + tid];
                s2 += pe[e+2]*linW[(e+2)*Hh + tid];
                s3 += pe[e+3]*linW[(e+3)*Hh + tid];
            }
            g_T[p*Hh + tid] = linb[tid] + (s0+s1) + (s2+s3);
        }
    } else if (bid == NPOS) {
        __shared__ int okt, okm;
        if (tid == 0) { okt = 1; okm = 1; }
        __syncthreads();
        const long long* t64 = (const long long*)tags;
        for (int i = tid; i < ntag/2; i += 320) {
            long long v = t64[i];
            if (v < 0 || v >= NPOS) okt = 0;
        }
        const long long* m64 = (const long long*)masks;
        for (int i = tid; i < nmask/2; i += 320) {
            long long v = m64[i];
            if (v < 0 || v > 1) okm = 0;
        }
        __syncthreads();
        if (tid == 0) { g_tag64 = okt; g_mask64 = okm; }
    } else if (bid == NPOS + 1) {
        __shared__ int okt2;
        __shared__ int cnt[Bb];
        if (tid == 0) okt2 = 1;
        if (tid < Bb) cnt[tid] = 0;
        __syncthreads();
        const long long* t64 = (const long long*)tags;
        for (int i = tid; i < ntag/2; i += 320) {
            long long v = t64[i];
            if (v < 0 || v >= NPOS) okt2 = 0;
        }
        __syncthreads();
        int is64 = okt2;
        for (int i = tid; i < Bb*Ss; i += 320) {
            int t = is64 ? (int)((const long long*)tags)[i] : ((const int*)tags)[i];
            if (t != 0) atomicAdd(&cnt[i/Ss], 1);
        }
        __syncthreads();
        if (tid < Bb) g_rlen[tid] = (float)cnt[tid];
        // counting-sort permutation of t by tag, per batch (one thread per b)
        if (tid < Bb) {
            int b = tid;
            unsigned short cbin[64];
            #pragma unroll
            for (int p = 0; p < 64; ++p) cbin[p] = 0;
            int tg[96];
            for (int t = 0; t < Ss; ++t) {
                int v = is64 ? (int)((const long long*)tags)[b*Ss + t]
                             : ((const int*)tags)[b*Ss + t];
                v = (v < 0) ? 0 : (v >= NPOS ? NPOS-1 : v);
                tg[t] = v;
                cbin[v]++;
            }
            int acc = 0;
            unsigned short start[64];
            #pragma unroll
            for (int p = 0; p < 64; ++p) {
                start[p] = (unsigned short)acc;
                g_segs[b][p] = (unsigned short)acc;
                acc += cbin[p];
            }
            g_segs[b][64] = (unsigned short)acc;  // == 96
            for (int t = 0; t < Ss; ++t)
                g_perm[b][start[tg[t]]++] = (unsigned short)t;
        }
    } else {
        int b = bid - (NPOS + 2);
        __shared__ float ts[Ee];
        __shared__ float msum[128];
        __shared__ int okm2;
        if (tid == 0) okm2 = 1;
        __syncthreads();
        const long long* m64 = (const long long*)masks;
        for (int i = tid; i < nmask/2; i += 320) {
            long long v = m64[i];
            if (v < 0 || v > 1) okm2 = 0;
        }
        for (int e = tid; e < Ee; e += 320) {
            const float* p = text + (size_t)b*Ll*Ee + e;
            float s0=0.f, s1=0.f, s2=0.f, s3=0.f;
            #pragma unroll 4
            for (int l = 0; l < Ll; l += 4) {
                s0 += p[(size_t)(l  )*Ee];
                s1 += p[(size_t)(l+1)*Ee];
                s2 += p[(size_t)(l+2)*Ee];
                s3 += p[(size_t)(l+3)*Ee];
            }
            ts[e] = (s0+s1) + (s2+s3);
        }
        __syncthreads();
        if (tid < 128) {
            long long v = okm2 ? ((const long long*)masks)[b*Ll + tid]
                               : (long long)((const int*)masks)[b*Ll + tid];
            msum[tid] = (float)v;
        }
        __syncthreads();
        for (int st = 64; st >= 1; st >>= 1) {
            if (tid < st) msum[tid] += msum[tid + st];
            __syncthreads();
        }
        float el = msum[0];
        if (tid < Hh) {
            float s0=0.f, s1=0.f, s2=0.f, s3=0.f;
            #pragma unroll 2
            for (int e = 0; e < Ee; e += 4) {
                s0 += ts[e  ]*linW[(e  )*Hh + tid];
                s1 += ts[e+1]*linW[(e+1)*Hh + tid];
                s2 += ts[e+2]*linW[(e+2)*Hh + tid];
                s3 += ts[e+3]*linW[(e+3)*Hh + tid];
            }
            float a = (s0+s1) + (s2+s3);
            g_hcmean[b*Hh + tid] = a/el + ((float)Ll/el)*linb[tid];
        }
    }
}

__device__ void d_wcvt(const float* __restrict__ rgcnW,
                       const float* __restrict__ scoreW,
                       int lr_, int ny, int kz) {
    int n0 = ny*32, k0 = kz*64;
    int l = lr_ / Rr;
    __shared__ float sm[64][33];
    __shared__ float swsh[32];
    int tid = threadIdx.x, tx = tid & 31, ty = tid >> 5;
    const float* W = rgcnW + (size_t)lr_*Hh*Hh;
    #pragma unroll
    for (int i = 0; i < 8; ++i) {
        int k = ty + i*8;
        int gk = k0 + k, gn = n0 + tx;
        sm[k][tx] = (gk < Hh && gn < Hh) ? W[(size_t)gk*Hh + gn] : 0.f;
    }
    if (tid < 32) {
        int gn = n0 + tid;
        swsh[tid] = (gn < Hh) ? scoreW[l*Hh + gn] : 0.f;
    }
    __syncthreads();
    uint32_t* out = g_wbf + (size_t)lr_*WNP*XKW;
    #pragma unroll
    for (int i = 0; i < 4; ++i) {
        int idx = i*256 + tid;
        int n = idx >> 5, k2 = idx & 31;
        int gn = n0 + n;
        if (gn < WNP)
            out[(size_t)gn*XKW + kz*32 + k2] = packbf(sm[2*k2][n], sm[2*k2+1][n]);
    }
    {
        int kl = tid >> 2, q = tid & 3;
        float p = 0.f;
        #pragma unroll
        for (int j = 0; j < 8; ++j) p += sm[kl][q*8 + j]*swsh[q*8 + j];
        p += __shfl_xor_sync(0xffffffffu, p, 1);
        p += __shfl_xor_sync(0xffffffffu, p, 2);
        if (q == 0 && k0 + kl < Hh)
            g_vpart[((size_t)lr_*10 + ny)*Hh + k0 + kl] = p;
    }
}

__device__ void d_gather(const void* __restrict__ tags, int idx) {
    const int N0 = Bb*Ss*XKW;
    if (idx < N0) {
        int kw = idx % XKW, bs = idx / XKW;
        if (kw < Hh/2) {
            int tg = load_tag(tags, bs);
            g_xbf[idx] = packbf(g_T[tg*Hh + 2*kw], g_T[tg*Hh + 2*kw + 1]);
        } else {
            g_xbf[idx] = 0u;
        }
    } else if (idx < N0 + 64*XKW) {
        int j = idx - N0;
        int kw = j % XKW, p = j / XKW;
        g_tbf[j] = (p < NPOS && kw < Hh/2)
                 ? packbf(g_T[p*Hh + 2*kw], g_T[p*Hh + 2*kw + 1]) : 0u;
    }
}

__device__ void d_vsum(int i) {
    if (i >= 2*48*XKW) return;
    int kw = i % XKW, lr2 = i / XKW;
    int l = lr2 / 48, r = lr2 % 48;
    float lo = 0.f, hi = 0.f;
    if (r < Rr && kw < Hh/2) {
        int lr_ = l*Rr + r;
        #pragma unroll
        for (int ny = 0; ny < 10; ++ny) {
            const float* vp = g_vpart + ((size_t)lr_*10 + ny)*Hh;
            lo += vp[2*kw]; hi += vp[2*kw + 1];
        }
    }
    g_vbf[i] = packbf(lo, hi);
}

// ---------------------------------------------------------------------------
// TH[r] = T @ W_r (tid < 128)
__device__ void d_thgemm(int oc, int r) {
    int tid = threadIdx.x, wid = tid >> 5, lane = tid & 31;
    int lq = lane >> 2, lr = lane & 3;
    int mw = wid >> 1, nw = wid & 1;

    extern __shared__ uint32_t smu[];
    uint32_t sm_sh = (uint32_t)__cvta_generic_to_shared(smu);
    const uint32_t wsOff = 64*KW*4;

    const uint32_t* wg = g_wbf + ((size_t)r*WNP + oc*104)*XKW;

    uint32_t aOff = (((mw*32 + (lane & 15))*KW + (lane >> 4)*4) << 2);
    int rw = lane & 7, grp = lane >> 3;
    uint32_t bRow = (grp >> 1)*8 + rw;
    uint32_t bWof = (grp & 1)*4;
    uint32_t rw2 = lane & 7, bW2 = ((lane >> 3) & 1)*4;
    int nBase = nw ? 56 : 0;

    float acc[2][7][4];
    #pragma unroll
    for (int t = 0; t < 2; ++t)
        #pragma unroll
        for (int j = 0; j < 7; ++j)
            #pragma unroll
            for (int q = 0; q < 4; ++q) acc[t][j][q] = 0.f;

    auto stage = [&](int kc, int bsel) {
        uint32_t base = sm_sh + bsel*(TBUF*4);
        #pragma unroll 1
        for (int i = tid; i < 1344; i += 128) {
            int row = i >> 3, q = i & 7;
            if (row < 64) {
                cpa16(base + ((row*KW + q*4) << 2), g_tbf + row*XKW + kc*32 + q*4);
            } else {
                int n = row - 64;
                cpa16(base + wsOff + ((n*KW + q*4) << 2),
                      wg + (size_t)n*XKW + kc*32 + q*4);
            }
        }
        CP_COMMIT();
    };

    stage(0, 0);
    for (int kc = 0; kc < 5; ++kc) {
        int bsel = kc & 1;
        if (kc < 4) { stage(kc + 1, bsel ^ 1); CP_WAIT(1); }
        else        { CP_WAIT(0); }
        __syncthreads();
        uint32_t base = sm_sh + bsel*(TBUF*4);
        #pragma unroll
        for (int ks = 0; ks < 4; ++ks) {
            uint32_t A[2][4];
            #pragma unroll
            for (int t = 0; t < 2; ++t)
                LDSM4(A[t][0], A[t][1], A[t][2], A[t][3],
                      base + aOff + (uint32_t)t*(16*KW*4) + ks*32);
            #pragma unroll
            for (int p = 0; p < 3; ++p) {
                uint32_t b0, b1, b2, b3;
                LDSM4(b0, b1, b2, b3,
                      base + wsOff + ((((nBase + p*16 + bRow)*KW + bWof) << 2) + ks*32));
                #pragma unroll
                for (int t = 0; t < 2; ++t) {
                    MMA_BF16(acc[t][2*p],   A[t][0],A[t][1],A[t][2],A[t][3], b0, b1);
                    MMA_BF16(acc[t][2*p+1], A[t][0],A[t][1],A[t][2],A[t][3], b2, b3);
                }
            }
            if (nw == 0) {
                uint32_t c0, c1;
                LDSM2(c0, c1, base + wsOff + ((((48 + rw2)*KW + bW2) << 2) + ks*32));
                #pragma unroll
                for (int t = 0; t < 2; ++t)
                    MMA_BF16(acc[t][6], A[t][0],A[t][1],A[t][2],A[t][3], c0, c1);
            }
        }
        __syncthreads();
    }
    int nt0 = nw*7, nts = nw ? 6 : 7;
    #pragma unroll
    for (int t = 0; t < 2; ++t) {
        int row = mw*32 + t*16 + lq;
        #pragma unroll
        for (int j = 0; j < 7; ++j) {
            if (j < nts) {
                int c = (nt0 + j)*8 + lr*2;
                size_t b0i = ((size_t)r*WNP + oc*104 + c)*64;
                size_t b1i = ((size_t)r*WNP + oc*104 + c + 1)*64;
                g_tht[b0i + row]     = (unsigned short)packbf(acc[t][j][0], 0.f);
                g_tht[b1i + row]     = (unsigned short)packbf(acc[t][j][1], 0.f);
                g_tht[b0i + row + 8] = (unsigned short)packbf(acc[t][j][2], 0.f);
                g_tht[b1i + row + 8] = (unsigned short)packbf(acc[t][j][3], 0.f);
            }
        }
    }
}

// ---------------------------------------------------------------------------
__device__ void d_ugemm(int l, int bp) {
    int tid = threadIdx.x, wid = tid >> 5, lane = tid & 31;
    int lq = lane >> 2, lr = lane & 3;
    int mw = wid >> 1, nw = wid & 1;

    extern __shared__ uint32_t smu[];
    uint32_t sm_sh = (uint32_t)__cvta_generic_to_shared(smu);
    const uint32_t vOff = 192*KW*4;

    const uint32_t* xg = g_xbf + (size_t)(bp*192)*XKW;
    const uint32_t* vg = g_vbf + (size_t)(l*48)*XKW;

    uint32_t aOff = (((mw*48 + (lane & 15))*KW + (lane >> 4)*4) << 2);
    int rw = lane & 7, grp = lane >> 3;
    uint32_t bRow = (grp >> 1)*8 + rw;
    uint32_t bWof = (grp & 1)*4;
    uint32_t rw2 = lane & 7, bW2 = ((lane >> 3) & 1)*4;
    int nBase = nw*24;

    float acc[3][3][4];
    #pragma unroll
    for (int t = 0; t < 3; ++t)
        #pragma unroll
        for (int j = 0; j < 3; ++j)
            #pragma unroll
            for (int q = 0; q < 4; ++q) acc[t][j][q] = 0.f;

    auto stage = [&](int kc, int bsel) {
        uint32_t base = sm_sh + bsel*(UBUF*4);
        #pragma unroll 1
        for (int i = tid; i < 1920; i += 256) {
            uint32_t dst; const uint32_t* src;
            int row = i >> 3, q = i & 7;
            if (row < 192) {
                dst = base + ((row*KW + q*4) << 2);
                src = xg + (size_t)row*XKW + kc*32 + q*4;
            } else {
                int vr = row - 192;
                dst = base + vOff + ((vr*KW + q*4) << 2);
                src = vg + (size_t)vr*XKW + kc*32 + q*4;
            }
            cpa16(dst, src);
        }
        CP_COMMIT();
    };

    stage(0, 0);
    for (int kc = 0; kc < 5; ++kc) {
        int bsel = kc & 1;
        if (kc < 4) { stage(kc + 1, bsel ^ 1); CP_WAIT(1); }
        else        { CP_WAIT(0); }
        __syncthreads();
        uint32_t base = sm_sh + bsel*(UBUF*4);
        #pragma unroll
        for (int ks = 0; ks < 4; ++ks) {
            uint32_t A[3][4];
            #pragma unroll
            for (int t = 0; t < 3; ++t)
                LDSM4(A[t][0], A[t][1], A[t][2], A[t][3],
                      base + aOff + (uint32_t)t*(16*KW*4) + ks*32);
            uint32_t b0, b1, b2, b3;
            LDSM4(b0, b1, b2, b3,
                  base + vOff + ((((nBase + bRow)*KW + bWof) << 2) + ks*32));
            uint32_t c0, c1;
            LDSM2(c0, c1, base + vOff + ((((nBase + 16 + rw2)*KW + bW2) << 2) + ks*32));
            #pragma unroll
            for (int t = 0; t < 3; ++t) {
                MMA_BF16(acc[t][0], A[t][0],A[t][1],A[t][2],A[t][3], b0, b1);
                MMA_BF16(acc[t][1], A[t][0],A[t][1],A[t][2],A[t][3], b2, b3);
                MMA_BF16(acc[t][2], A[t][0],A[t][1],A[t][2],A[t][3], c0, c1);
            }
        }
        __syncthreads();
    }
    #pragma unroll
    for (int t = 0; t < 3; ++t) {
        int row0 = mw*48 + t*16 + lq;
        #pragma unroll
        for (int j = 0; j < 3; ++j) {
            int c = nBase + j*8 + lr*2;
            #pragma unroll
            for (int h = 0; h < 2; ++h) {
                int row = row0 + h*8;
                int b = bp*2 + (row >= 96), s = row & 95;
                if (c < Rr)     g_u[(b*Rr + c)*Ss + s]     = acc[t][j][2*h];
                if (c + 1 < Rr) g_u[(b*Rr + c + 1)*Ss + s] = acc[t][j][2*h + 1];
            }
        }
    }
}

// ---------------------------------------------------------------------------
// Fused scores + softmax + (A' | Ac) build.  Grid (b, 4), 256 threads.
__device__ void d_sap(const float* __restrict__ adj, int b, int sq, int l) {
    int s0 = sq*SQ;
    __shared__ float usm[Rr][Ss];
    __shared__ float scs[Rr][SQ];
    __shared__ float dns[Rr][SQ];
    __shared__ float wds[Rr][SQ];
    int tid = threadIdx.x;
    for (int i = tid; i < Rr*Ss; i += 256) usm[i/Ss][i%Ss] = g_u[b*Rr*Ss + i];
    __syncthreads();
    for (int i = tid; i < Rr*SQ; i += 256) {
        int r = i / SQ, t = i % SQ;
        const float4* ar = (const float4*)(adj + (((size_t)b*Rr + r)*Ss + s0 + t)*Ss);
        const float* u = usm[r];
        float d = 0.f, sr = 0.f;
        #pragma unroll 6
        for (int j = 0; j < Ss/4; ++j) {
            float4 av = ar[j];
            d  += av.x + av.y + av.z + av.w;
            sr += av.x*u[4*j] + av.y*u[4*j+1] + av.z*u[4*j+2] + av.w*u[4*j+3];
        }
        float ds = (d == 0.f) ? 1.f : d;
        scs[r][t] = sr/ds;
        dns[r][t] = ds;
    }
    __syncthreads();
    if (tid < SQ) {
        int t = tid;
        float mx = -1e30f;
        for (int r = 0; r < Rr; ++r) mx = fmaxf(mx, scs[r][t]);
        float Z = 0.f;
        for (int r = 0; r < Rr; ++r) Z += expf(scs[r][t] - mx);
        for (int r = 0; r < Rr; ++r)
            wds[r][t] = expf(scs[r][t] - mx) / (Z * dns[r][t]);
    }
    __syncthreads();
    if (l == 1) {
        for (int i = tid; i < Rr*SQ*(Ss/4); i += 256) {
            int r = i / (SQ*(Ss/4)), rem = i % (SQ*(Ss/4));
            int t = rem / (Ss/4), q = rem % (Ss/4);
            const float4* ar = (const float4*)(adj + (((size_t)b*Rr + r)*Ss + s0 + t)*Ss);
            float4 av = ar[q];
            float w = wds[r][t];
            uint32_t* out = g_apbf + ((size_t)(b*Rr + r))*Ss*48 + (size_t)(s0 + t)*48;
            out[2*q]     = packbf(av.x*w, av.y*w);
            out[2*q + 1] = packbf(av.z*w, av.w*w);
        }
    } else {
        // tag-compressed Ac[s][p] = w[s] * sum_{t: tag[t]=p} adj[s][t]
        __shared__ float adjsm[SQ][100];
        __shared__ unsigned short permS[96];
        __shared__ unsigned short segsS[65];
        if (tid < 96) permS[tid] = g_perm[b][tid];
        if (tid < 65) segsS[tid] = g_segs[b][tid];
        for (int r = 0; r < Rr; ++r) {
            __syncthreads();
            for (int i = tid; i < SQ*24; i += 256) {
                int s = i / 24, q4 = i % 24;
                const float4* ar = (const float4*)(adj + (((size_t)b*Rr + r)*Ss + s0 + s)*Ss);
                *(float4*)&adjsm[s][q4*4] = ar[q4];
            }
            __syncthreads();
            for (int i = tid; i < SQ*32; i += 256) {
                int s = i >> 5, p2 = i & 31;
                float w = wds[r][s];
                int p0 = 2*p2;
                float a0 = 0.f, a1 = 0.f;
                for (int j = segsS[p0]; j < segsS[p0+1]; ++j) a0 += adjsm[s][permS[j]];
                for (int j = segsS[p0+1]; j < segsS[p0+2]; ++j) a1 += adjsm[s][permS[j]];
                g_acbf[((size_t)(b*Rr + r)*Ss + s0 + s)*32 + p2] = packbf(a0*w, a1*w);
            }
        }
    }
}

// ---------------------------------------------------------------------------
__device__ void d_hidgemm(int l, int bp, int oc, int r) {
    int tid = threadIdx.x, wid = tid >> 5, lane = tid & 31;
    int lq = lane >> 2, lr = lane & 3;
    int mw = wid >> 1, nw = wid & 1;

    extern __shared__ uint32_t smu[];
    uint32_t sm_sh = (uint32_t)__cvta_generic_to_shared(smu);

    const uint32_t* xg = g_xbf + (size_t)(bp*2)*Ss*XKW;
    const uint32_t* wg = g_wbf + ((size_t)(l*Rr + r)*WNP + oc*OCW)*XKW;

    const uint32_t wsOff = 192*KW*4;

    uint32_t aOff = (((mw*48 + (lane & 15))*KW + (lane >> 4)*4) << 2);
    int rw = lane & 7, grp = lane >> 3;
    uint32_t bRow = (grp >> 1)*8 + rw;
    uint32_t bWof = (grp & 1)*4;
    uint32_t rw2 = lane & 7, bW2 = ((lane >> 3) & 1)*4;
    int nBase = nw ? 56 : 0;

    float acc[3][7][4];
    #pragma unroll
    for (int t = 0; t < 3; ++t)
        #pragma unroll
        for (int j = 0; j < 7; ++j)
            #pragma unroll
            for (int q = 0; q < 4; ++q) acc[t][j][q] = 0.f;

    auto stage = [&](int kc, int bsel) {
        uint32_t base = sm_sh + bsel*(ABUF2*4);
        #pragma unroll 1
        for (int i = tid; i < 2368; i += 256) {
            uint32_t dst; const uint32_t* src;
            if (i < 1536) {
                int row = i >> 3, q = i & 7;
                dst = base + ((row*KW + q*4) << 2);
                src = xg + row*XKW + kc*32 + q*4;
            } else {
                int j = i - 1536;
                int row = j >> 3, q = j & 7;
                dst = base + wsOff + ((row*KW + q*4) << 2);
                src = wg + (size_t)row*XKW + kc*32 + q*4;
            }
            cpa16(dst, src);
        }
        CP_COMMIT();
    };

    stage(0, 0);
    for (int kc = 0; kc < 5; ++kc) {
        int bsel = kc & 1;
        if (kc < 4) { stage(kc + 1, bsel ^ 1); CP_WAIT(1); }
        else        { CP_WAIT(0); }
        __syncthreads();
        uint32_t base = sm_sh + bsel*(ABUF2*4);
        #pragma unroll
        for (int ks = 0; ks < 4; ++ks) {
            uint32_t A[3][4];
            #pragma unroll
            for (int t = 0; t < 3; ++t)
                LDSM4(A[t][0], A[t][1], A[t][2], A[t][3],
                      base + aOff + (uint32_t)t*(16*KW*4) + ks*32);
            #pragma unroll
            for (int p = 0; p < 3; ++p) {
                uint32_t b0, b1, b2, b3;
                LDSM4(b0, b1, b2, b3,
                      base + wsOff + ((((nBase + p*16 + bRow)*KW + bWof) << 2) + ks*32));
                #pragma unroll
                for (int t = 0; t < 3; ++t) {
                    MMA_BF16(acc[t][2*p],   A[t][0],A[t][1],A[t][2],A[t][3], b0, b1);
                    MMA_BF16(acc[t][2*p+1], A[t][0],A[t][1],A[t][2],A[t][3], b2, b3);
                }
            }
            if (nw == 0) {
                uint32_t c0, c1;
                LDSM2(c0, c1, base + wsOff + ((((48 + rw2)*KW + bW2) << 2) + ks*32));
                #pragma unroll
                for (int t = 0; t < 3; ++t)
                    MMA_BF16(acc[t][6], A[t][0],A[t][1],A[t][2],A[t][3], c0, c1);
            }
        }
        __syncthreads();
    }
    {
        int b_local = mw >> 1;
        int rloc = mw*48 - b_local*96;
        __nv_bfloat16* hidB = (__nv_bfloat16*)(smu + b_local*ABUF2);
        int nt0 = nw*7, nts = nw ? 6 : 7;
        #pragma unroll
        for (int t = 0; t < 3; ++t) {
            int row = rloc + t*16 + lq;
            #pragma unroll
            for (int j = 0; j < 7; ++j) {
                if (j < nts) {
                    int c = (nt0 + j)*8 + lr*2;
                    hidB[(size_t)c*(2*TW) + row]         = __float2bfloat16_rn(acc[t][j][0]);
                    hidB[(size_t)(c+1)*(2*TW) + row]     = __float2bfloat16_rn(acc[t][j][1]);
                    hidB[(size_t)c*(2*TW) + row + 8]     = __float2bfloat16_rn(acc[t][j][2]);
                    hidB[(size_t)(c+1)*(2*TW) + row + 8] = __float2bfloat16_rn(acc[t][j][3]);
                }
            }
        }
    }
    __syncthreads();
    #pragma unroll
    for (int bi = 0; bi < 2; ++bi) {
        uint32_t* hg = g_hid + ((size_t)(r*Bb + bp*2 + bi)*3 + oc)*HCH;
        const uint32_t* src = smu + bi*ABUF2;
        #pragma unroll 4
        for (int i = tid; i < HCH; i += 256) hg[i] = src[i];
    }
}

// ---------------------------------------------------------------------------
// Merged launch kernels
__global__ void __launch_bounds__(320)
k_pre1(const float* __restrict__ posemb, const float* __restrict__ linW,
       const float* __restrict__ linb, const float* __restrict__ text,
       const float* __restrict__ rgcnW, const float* __restrict__ scoreW,
       const void* tags, const void* masks, int ntag, int nmask) {
    int bx = blockIdx.x;
    if (bx < 4100) {
        if (threadIdx.x >= 256) return;
        d_wcvt(rgcnW, scoreW, bx % 82, (bx/82) % 10, bx/820);
    } else {
        d_detpost(posemb, linW, linb, text, tags, masks, ntag, nmask, bx - 4100);
    }
}

__global__ void k_pre2(const void* tags) {
    int bx = blockIdx.x;
    if (bx < 1960) d_gather(tags, bx*256 + threadIdx.x);
    else           d_vsum((bx - 1960)*256 + threadIdx.x);
}

__global__ void __launch_bounds__(256)
k_pre3() {
    int bx = blockIdx.x;
    if (bx < 123) {
        if (threadIdx.x >= 128) return;
        d_thgemm(bx % 3, bx / 3);
    } else {
        d_ugemm(0, bx - 123);
    }
}

__global__ void __launch_bounds__(256)
k_sap(const float* __restrict__ adj, int l) {
    d_sap(adj, blockIdx.x, blockIdx.y, l);
}

__global__ void __launch_bounds__(256, 2)
k_l1a() {
    int bx = blockIdx.x;
    if (bx < 1968) d_hidgemm(1, bx % 16, (bx/16) % 3, bx/48);
    else           d_ugemm(1, bx - 1968);
}

// ---------------------------------------------------------------------------
// GEMM B dual-mode:
//  l=1: part += A'(96xK96) @ hid(104xK96)   (strides TW)
//  l=0: part += Ac(96xK64) @ TH(104xK64)    (strides KW), TH shared across b
__global__ void __launch_bounds__(192)
k_pass2b(int l) {
    int b = blockIdx.x, oc = blockIdx.y, g = blockIdx.z;
    int tid = threadIdx.x, wid = tid >> 5, lane = tid & 31;
    int lq = lane >> 2, lr = lane & 3;
    int mw = wid % 3, nw = wid / 3;
    int r0 = g*14, nr = (g == 2) ? 13 : 14;

    extern __shared__ uint32_t smu[];
    uint32_t sm_sh = (uint32_t)__cvta_generic_to_shared(smu);

    const int AST = l ? TW : KW;
    const uint32_t bReg = l ? (96*TW*4) : (96*KW*4);
    const int KS = l ? 6 : 4;

    uint32_t aOff = (((mw*32 + (lane & 15))*AST + (lane >> 4)*4) << 2);
    int rw = lane & 7, grp = lane >> 3;
    uint32_t bRow = (grp >> 1)*8 + rw;
    uint32_t bWof = (grp & 1)*4;
    uint32_t rw2 = lane & 7, bW2 = ((lane >> 3) & 1)*4;
    int nBase = nw ? 56 : 0;

    float acc[2][7][4];
    #pragma unroll
    for (int t = 0; t < 2; ++t)
        #pragma unroll
        for (int j = 0; j < 7; ++j)
            #pragma unroll
            for (int q = 0; q < 4; ++q) acc[t][j][q] = 0.f;

    auto stage = [&](int rr, int bsel) {
        int r = r0 + rr;
        uint32_t base = sm_sh + bsel*(BBUF*4);
        if (l) {
            const uint32_t* ag = g_apbf + ((size_t)(b*Rr + r))*Ss*48;
            const uint32_t* hg = g_hid + ((size_t)(r*Bb + b)*3 + oc)*HCH;
            #pragma unroll 1
            for (int i = tid; i < 2504; i += 192) {
                uint32_t dst; const uint32_t* src;
                if (i < 1152) {
                    int row = i / 12, q = i % 12;
                    dst = base + ((row*TW + q*4) << 2);
                    src = ag + row*48 + q*4;
                } else {
                    int j = i - 1152;
                    dst = base + bReg + (j << 4);
                    src = hg + j*4;
                }
                cpa16(dst, src);
            }
        } else {
            const uint32_t* ag = g_acbf + ((size_t)(b*Rr + r))*Ss*32;
            const uint32_t* tg = (const uint32_t*)(g_tht + ((size_t)r*WNP + oc*OCW)*64);
            #pragma unroll 1
            for (int i = tid; i < 1600; i += 192) {
                uint32_t dst; const uint32_t* src;
                if (i < 768) {
                    int row = i >> 3, q = i & 7;
                    dst = base + ((row*KW + q*4) << 2);
                    src = ag + row*32 + q*4;
                } else {
                    int j = i - 768;
                    int row = j >> 3, q = j & 7;
                    dst = base + bReg + ((row*KW + q*4) << 2);
                    src = tg + row*32 + q*4;
                }
                cpa16(dst, src);
            }
        }
        CP_COMMIT();
    };

    stage(0, 0);
    for (int rr = 0; rr < nr; ++rr) {
        int bsel = rr & 1;
        if (rr + 1 < nr) { stage(rr + 1, bsel ^ 1); CP_WAIT(1); }
        else             { CP_WAIT(0); }
        __syncthreads();
        uint32_t base = sm_sh + bsel*(BBUF*4);
        #pragma unroll 2
        for (int ks = 0; ks < KS; ++ks) {
            uint32_t A[2][4];
            #pragma unroll
            for (int t = 0; t < 2; ++t)
                LDSM4(A[t][0], A[t][1], A[t][2], A[t][3],
                      base + aOff + (uint32_t)t*(16*AST*4) + ks*32);
            #pragma unroll
            for (int p = 0; p < 3; ++p) {
                uint32_t b0, b1, b2, b3;
                LDSM4(b0, b1, b2, b3,
                      base + bReg + ((((nBase + p*16 + bRow)*AST + bWof) << 2) + ks*32));
                #pragma unroll
                for (int t = 0; t < 2; ++t) {
                    MMA_BF16(acc[t][2*p],   A[t][0],A[t][1],A[t][2],A[t][3], b0, b1);
                    MMA_BF16(acc[t][2*p+1], A[t][0],A[t][1],A[t][2],A[t][3], b2, b3);
                }
            }
            if (nw == 0) {
                uint32_t c0, c1;
                LDSM2(c0, c1, base + bReg + ((((48 + rw2)*AST + bW2) << 2) + ks*32));
                #pragma unroll
                for (int t = 0; t < 2; ++t)
                    MMA_BF16(acc[t][6], A[t][0],A[t][1],A[t][2],A[t][3], c0, c1);
            }
        }
        __syncthreads();
    }

    float* pp = g_part + ((size_t)(b*NG + g))*Ss*Hh;
    int o0 = oc*OCW;
    int nt0 = nw*7, nts = nw ? 6 : 7;
    #pragma unroll
    for (int t = 0; t < 2; ++t) {
        int row = mw*32 + t*16 + lq;
        #pragma unroll
        for (int j = 0; j < 7; ++j) {
            if (j < nts) {
                int c = (nt0 + j)*8 + lr*2;
                if (c < OCW) {
                    pp[row*Hh + o0 + c]         = acc[t][j][0];
                    pp[row*Hh + o0 + c + 1]     = acc[t][j][1];
                    pp[(row+8)*Hh + o0 + c]     = acc[t][j][2];
                    pp[(row+8)*Hh + o0 + c + 1] = acc[t][j][3];
                }
            }
        }
    }
}

// x_out = relu(sum over groups): l=0 -> packed bf16x2; l=1 -> fp32 for pooling
__global__ void k_reduce(int l) {
    int idx = blockIdx.x*blockDim.x + threadIdx.x;
    if (l == 0) {
        if (idx >= Bb*Ss*XKW) return;
        int kw = idx % XKW, bs = idx / XKW;
        if (kw >= Hh/2) return;
        int b = bs / Ss;
        size_t inner = (size_t)(bs % Ss)*Hh + 2*kw;
        float a0 = 0.f, a1 = 0.f;
        #pragma unroll
        for (int g = 0; g < NG; ++g) {
            const float* pp = g_part + ((size_t)(b*NG + g))*Ss*Hh + inner;
            a0 += pp[0]; a1 += pp[1];
        }
        g_xbf[idx] = packbf(fmaxf(a0, 0.f), fmaxf(a1, 0.f));
    } else {
        if (idx >= Bb*Ss*(Hh/2)) return;
        int kw = idx % (Hh/2), bs = idx / (Hh/2);
        int b = bs / Ss;
        size_t inner = (size_t)(bs % Ss)*Hh + 2*kw;
        float a0 = 0.f, a1 = 0.f;
        #pragma unroll
        for (int g = 0; g < NG; ++g) {
            const float* pp = g_part + ((size_t)(b*NG + g))*Ss*Hh + inner;
            a0 += pp[0]; a1 += pp[1];
        }
        *(float2*)&g_x0[(size_t)bs*Hh + 2*kw] =
            make_float2(fmaxf(a0, 0.f), fmaxf(a1, 0.f));
    }
}

// ---------------------------------------------------------------------------
__global__ void k_final(const float* __restrict__ dW, const float* __restrict__ db,
                        float* __restrict__ out) {
    int b = blockIdx.x, tid = threadIdx.x;  // 320
    __shared__ float red0[320], red1[320], red2[320];
    float p0 = 0.f, p1 = 0.f, p2 = 0.f;
    if (tid < Hh) {
        float a = 0.f;
        for (int s = 0; s < Ss; ++s) a += g_x0[((size_t)b*Ss + s)*Hh + tid];
        float hg = a / g_rlen[b];
        float hc = g_hcmean[b*Hh + tid];
        p0 = hg*dW[tid*NLAB + 0] + hc*dW[(Hh + tid)*NLAB + 0];
        p1 = hg*dW[tid*NLAB + 1] + hc*dW[(Hh + tid)*NLAB + 1];
        p2 = hg*dW[tid*NLAB + 2] + hc*dW[(Hh + tid)*NLAB + 2];
    }
    red0[tid] = p0; red1[tid] = p1; red2[tid] = p2;
    __syncthreads();
    for (int st = 160; st >= 5; st >>= 1) {
        if (tid < st) {
            red0[tid] += red0[tid + st];
            red1[tid] += red1[tid + st];
            red2[tid] += red2[tid + st];
        }
        __syncthreads();
    }
    if (tid < NLAB) {
        float* rn = (tid == 0) ? red0 : (tid == 1) ? red1 : red2;
        float a = db[tid];
        #pragma unroll
        for (int i = 0; i < 5; ++i) a += rn[i];
        out[b*NLAB + tid] = a;
    }
}

// ---------------------------------------------------------------------------
extern "C" void kernel_launch(void* const* d_in, const int* in_sizes, int n_in,
                              void* d_out, int out_size) {
    const float* text   = (const float*)d_in[0];
    const void*  masks  = d_in[1];
    const void*  tags   = d_in[2];
    const float* adj    = (const float*)d_in[3];
    const float* posemb = (const float*)d_in[4];
    const float* linW   = (const float*)d_in[5];
    const float* linb   = (const float*)d_in[6];
    const float* rgcnW  = (const float*)d_in[7];
    const float* scoreW = (const float*)d_in[8];
    // d_in[9] = score_b: softmax over relations is invariant to it — unused
    const float* dW     = (const float*)d_in[10];
    const float* db     = (const float*)d_in[11];
    float*       out    = (float*)d_out;

    const int SMEM_P3 = 2*UBUF*4;    // 69120
    const int SMEM_L1 = 2*ABUF2*4;   // 85248
    const int SMEM_B  = 2*BBUF*4;    // 83200
    cudaFuncSetAttribute(k_pre3,  cudaFuncAttributeMaxDynamicSharedMemorySize, SMEM_P3);
    cudaFuncSetAttribute(k_l1a,   cudaFuncAttributeMaxDynamicSharedMemorySize, SMEM_L1);
    cudaFuncSetAttribute(k_pass2b, cudaFuncAttributeMaxDynamicSharedMemorySize, SMEM_B);

    k_pre1<<<4100 + NPOS + 2 + Bb, 320>>>(posemb, linW, linb, text, rgcnW, scoreW,
                                          tags, masks, in_sizes[2], in_sizes[1]);
    k_pre2<<<1960 + 60, 256>>>(tags);
    k_pre3<<<123 + 16, 256, SMEM_P3>>>();
    k_sap<<<dim3(Bb, 4), 256>>>(adj, 0);            // ncu capture slot (idx 3)
    k_pass2b<<<dim3(Bb, 3, NG), 192, SMEM_B>>>(0);
    k_reduce<<<(Bb*Ss*XKW + 255)/256, 256>>>(0);
    k_l1a<<<1968 + 16, 256, SMEM_L1>>>();
    k_sap<<<dim3(Bb, 4), 256>>>(adj, 1);
    k_pass2b<<<dim3(Bb, 3, NG), 192, SMEM_B>>>(1);
    k_reduce<<<(Bb*Ss*XKW + 255)/256, 256>>>(1);
    k_final<<<Bb, 320>>>(dW, db, out);
}

// round 16
// speedup vs baseline: 1.1727x; 1.1727x over previous
#include <cuda_runtime.h>
#include <cuda_bf16.h>
#include <math.h>
#include <stdint.h>

// Problem constants
#define Bb 32
#define Ll 128
#define Ss 96
#define Ee 768
#define Hh 300
#define Rr 41
#define NPOS 50
#define NLAB 3
#define NG 3        // relation groups (14,14,13)
#define OCW 100
#define SQ 24       // s-rows per sap block

// packed layouts
#define XKW 160
#define WNP 312
#define KW  36
#define TW  52
#define HCH 5408
#define ABUF2 (192*KW + 104*KW)   // 10656 words
#define TBUF  (64*KW + 104*KW)    // 6048 words
#define UBUF  (192*KW + 48*KW)    // 8640 words
#define BBUF 10400

// Scratch (device globals — no allocations allowed)
__device__ float    g_hcmean[Bb*Hh];
__device__ float    g_T[NPOS*Hh];
__device__ float    g_x0[Bb*Ss*Hh];
__device__ float    g_rlen[Bb];
__device__ float    g_vpart[2*Rr*10*Hh];
__device__ float    g_u[Bb*Rr*Ss];
__device__ float    g_wd[Bb*Rr*Ss];
__device__ float    g_part[(size_t)Bb*NG*Ss*Hh];
__device__ int      g_tag64;
__device__ int      g_mask64;
__device__ unsigned short g_perm[Bb][96];
__device__ unsigned short g_segs[Bb][65];
__device__ uint32_t g_xbf[Bb*Ss*XKW];
__device__ uint32_t g_tbf[64*XKW];
__device__ unsigned short g_tht[(size_t)Rr*WNP*64];
__device__ uint32_t g_vbf[2*48*XKW];
__device__ uint32_t g_wbf[(size_t)2*Rr*WNP*XKW];
__device__ uint32_t g_hid[(size_t)Rr*Bb*3*HCH];
__device__ uint32_t g_apbf[(size_t)Bb*Rr*Ss*48];
__device__ uint32_t g_acbf[(size_t)Bb*Rr*Ss*32];

__device__ __forceinline__ uint32_t packbf(float lo, float hi) {
    uint32_t d;
    asm("cvt.rn.bf16x2.f32 %0, %1, %2;" : "=r"(d) : "f"(hi), "f"(lo));
    return d;
}

__device__ __forceinline__ int load_tag(const void* tags, int idx) {
    int t;
    if (g_tag64) t = (int)((const long long*)tags)[idx];
    else         t = ((const int*)tags)[idx];
    return (t < 0) ? 0 : (t >= NPOS ? NPOS-1 : t);
}

__device__ __forceinline__ void cpa16(uint32_t dst_sh, const void* src) {
    asm volatile("cp.async.ca.shared.global [%0], [%1], 16;" :: "r"(dst_sh), "l"(src));
}
#define CP_COMMIT() asm volatile("cp.async.commit_group;")
#define CP_WAIT(n)  asm volatile("cp.async.wait_group %0;" :: "n"(n))

#define MMA_BF16(c, a0,a1,a2,a3, b0,b1) \
    asm volatile("mma.sync.aligned.m16n8k16.row.col.f32.bf16.bf16.f32 " \
        "{%0,%1,%2,%3}, {%4,%5,%6,%7}, {%8,%9}, {%0,%1,%2,%3};" \
        : "+f"((c)[0]), "+f"((c)[1]), "+f"((c)[2]), "+f"((c)[3]) \
        : "r"(a0), "r"(a1), "r"(a2), "r"(a3), "r"(b0), "r"(b1))

#define LDSM4(r0,r1,r2,r3, addr) \
    asm volatile("ldmatrix.sync.aligned.m8n8.x4.shared.b16 {%0,%1,%2,%3}, [%4];" \
        : "=r"(r0), "=r"(r1), "=r"(r2), "=r"(r3) : "r"(addr))

#define LDSM2(r0,r1, addr) \
    asm volatile("ldmatrix.sync.aligned.m8n8.x2.shared.b16 {%0,%1}, [%2];" \
        : "=r"(r0), "=r"(r1) : "r"(addr))

// ---------------------------------------------------------------------------
__device__ void d_detpost(const float* __restrict__ posemb,
                          const float* __restrict__ linW,
                          const float* __restrict__ linb,
                          const float* __restrict__ text,
                          const void* tags, const void* masks,
                          int ntag, int nmask, int bid) {
    int tid = threadIdx.x;  // 320
    if (bid < NPOS) {
        int p = bid;
        __shared__ float pe[Ee];
        for (int e = tid; e < Ee; e += 320) pe[e] = posemb[p*Ee + e];
        __syncthreads();
        if (tid < Hh) {
            float s0=0.f, s1=0.f, s2=0.f, s3=0.f;
            #pragma unroll 2
            for (int e = 0; e < Ee; e += 4) {
                s0 += pe[e  ]*linW[(e  )*Hh + tid];
                s1 += pe[e+1]*linW[(e+1)*Hh + tid];
                s2 += pe[e+2]*linW[(e+2)*Hh + tid];
                s3 += pe[e+3]*linW[(e+3)*Hh + tid];
            }
            g_T[p*Hh + tid] = linb[tid] + (s0+s1) + (s2+s3);
        }
    } else if (bid == NPOS) {
        __shared__ int okt, okm;
        if (tid == 0) { okt = 1; okm = 1; }
        __syncthreads();
        const long long* t64 = (const long long*)tags;
        for (int i = tid; i < ntag/2; i += 320) {
            long long v = t64[i];
            if (v < 0 || v >= NPOS) okt = 0;
        }
        const long long* m64 = (const long long*)masks;
        for (int i = tid; i < nmask/2; i += 320) {
            long long v = m64[i];
            if (v < 0 || v > 1) okm = 0;
        }
        __syncthreads();
        if (tid == 0) { g_tag64 = okt; g_mask64 = okm; }
    } else if (bid == NPOS + 1) {
        __shared__ int okt2;
        __shared__ int cnt[Bb];
        if (tid == 0) okt2 = 1;
        if (tid < Bb) cnt[tid] = 0;
        __syncthreads();
        const long long* t64 = (const long long*)tags;
        for (int i = tid; i < ntag/2; i += 320) {
            long long v = t64[i];
            if (v < 0 || v >= NPOS) okt2 = 0;
        }
        __syncthreads();
        int is64 = okt2;
        for (int i = tid; i < Bb*Ss; i += 320) {
            int t = is64 ? (int)((const long long*)tags)[i] : ((const int*)tags)[i];
            if (t != 0) atomicAdd(&cnt[i/Ss], 1);
        }
        __syncthreads();
        if (tid < Bb) g_rlen[tid] = (float)cnt[tid];
        // counting-sort permutation of t by tag, per batch (one thread per b)
        if (tid < Bb) {
            int b = tid;
            unsigned short cbin[64];
            #pragma unroll
            for (int p = 0; p < 64; ++p) cbin[p] = 0;
            int tg[96];
            for (int t = 0; t < Ss; ++t) {
                int v = is64 ? (int)((const long long*)tags)[b*Ss + t]
                             : ((const int*)tags)[b*Ss + t];
                v = (v < 0) ? 0 : (v >= NPOS ? NPOS-1 : v);
                tg[t] = v;
                cbin[v]++;
            }
            int acc = 0;
            unsigned short start[64];
            #pragma unroll
            for (int p = 0; p < 64; ++p) {
                start[p] = (unsigned short)acc;
                g_segs[b][p] = (unsigned short)acc;
                acc += cbin[p];
            }
            g_segs[b][64] = (unsigned short)acc;  // == 96
            for (int t = 0; t < Ss; ++t)
                g_perm[b][start[tg[t]]++] = (unsigned short)t;
        }
    } else {
        int b = bid - (NPOS + 2);
        __shared__ float ts[Ee];
        __shared__ float msum[128];
        __shared__ int okm2;
        if (tid == 0) okm2 = 1;
        __syncthreads();
        const long long* m64 = (const long long*)masks;
        for (int i = tid; i < nmask/2; i += 320) {
            long long v = m64[i];
            if (v < 0 || v > 1) okm2 = 0;
        }
        for (int e = tid; e < Ee; e += 320) {
            const float* p = text + (size_t)b*Ll*Ee + e;
            float s0=0.f, s1=0.f, s2=0.f, s3=0.f;
            #pragma unroll 4
            for (int l = 0; l < Ll; l += 4) {
                s0 += p[(size_t)(l  )*Ee];
                s1 += p[(size_t)(l+1)*Ee];
                s2 += p[(size_t)(l+2)*Ee];
                s3 += p[(size_t)(l+3)*Ee];
            }
            ts[e] = (s0+s1) + (s2+s3);
        }
        __syncthreads();
        if (tid < 128) {
            long long v = okm2 ? ((const long long*)masks)[b*Ll + tid]
                               : (long long)((const int*)masks)[b*Ll + tid];
            msum[tid] = (float)v;
        }
        __syncthreads();
        for (int st = 64; st >= 1; st >>= 1) {
            if (tid < st) msum[tid] += msum[tid + st];
            __syncthreads();
        }
        float el = msum[0];
        if (tid < Hh) {
            float s0=0.f, s1=0.f, s2=0.f, s3=0.f;
            #pragma unroll 2
            for (int e = 0; e < Ee; e += 4) {
                s0 += ts[e  ]*linW[(e  )*Hh + tid];
                s1 += ts[e+1]*linW[(e+1)*Hh + tid];
                s2 += ts[e+2]*linW[(e+2)*Hh + tid];
                s3 += ts[e+3]*linW[(e+3)*Hh + tid];
            }
            float a = (s0+s1) + (s2+s3);
            g_hcmean[b*Hh + tid] = a/el + ((float)Ll/el)*linb[tid];
        }
    }
}

__device__ void d_wcvt(const float* __restrict__ rgcnW,
                       const float* __restrict__ scoreW,
                       int lr_, int ny, int kz) {
    int n0 = ny*32, k0 = kz*64;
    int l = lr_ / Rr;
    __shared__ float sm[64][33];
    __shared__ float swsh[32];
    int tid = threadIdx.x, tx = tid & 31, ty = tid >> 5;
    const float* W = rgcnW + (size_t)lr_*Hh*Hh;
    #pragma unroll
    for (int i = 0; i < 8; ++i) {
        int k = ty + i*8;
        int gk = k0 + k, gn = n0 + tx;
        sm[k][tx] = (gk < Hh && gn < Hh) ? W[(size_t)gk*Hh + gn] : 0.f;
    }
    if (tid < 32) {
        int gn = n0 + tid;
        swsh[tid] = (gn < Hh) ? scoreW[l*Hh + gn] : 0.f;
    }
    __syncthreads();
    uint32_t* out = g_wbf + (size_t)lr_*WNP*XKW;
    #pragma unroll
    for (int i = 0; i < 4; ++i) {
        int idx = i*256 + tid;
        int n = idx >> 5, k2 = idx & 31;
        int gn = n0 + n;
        if (gn < WNP)
            out[(size_t)gn*XKW + kz*32 + k2] = packbf(sm[2*k2][n], sm[2*k2+1][n]);
    }
    {
        int kl = tid >> 2, q = tid & 3;
        float p = 0.f;
        #pragma unroll
        for (int j = 0; j < 8; ++j) p += sm[kl][q*8 + j]*swsh[q*8 + j];
        p += __shfl_xor_sync(0xffffffffu, p, 1);
        p += __shfl_xor_sync(0xffffffffu, p, 2);
        if (q == 0 && k0 + kl < Hh)
            g_vpart[((size_t)lr_*10 + ny)*Hh + k0 + kl] = p;
    }
}

__device__ void d_gather(const void* __restrict__ tags, int idx) {
    const int N0 = Bb*Ss*XKW;
    if (idx < N0) {
        int kw = idx % XKW, bs = idx / XKW;
        if (kw < Hh/2) {
            int tg = load_tag(tags, bs);
            g_xbf[idx] = packbf(g_T[tg*Hh + 2*kw], g_T[tg*Hh + 2*kw + 1]);
        } else {
            g_xbf[idx] = 0u;
        }
    } else if (idx < N0 + 64*XKW) {
        int j = idx - N0;
        int kw = j % XKW, p = j / XKW;
        g_tbf[j] = (p < NPOS && kw < Hh/2)
                 ? packbf(g_T[p*Hh + 2*kw], g_T[p*Hh + 2*kw + 1]) : 0u;
    }
}

__device__ void d_vsum(int i) {
    if (i >= 2*48*XKW) return;
    int kw = i % XKW, lr2 = i / XKW;
    int l = lr2 / 48, r = lr2 % 48;
    float lo = 0.f, hi = 0.f;
    if (r < Rr && kw < Hh/2) {
        int lr_ = l*Rr + r;
        #pragma unroll
        for (int ny = 0; ny < 10; ++ny) {
            const float* vp = g_vpart + ((size_t)lr_*10 + ny)*Hh;
            lo += vp[2*kw]; hi += vp[2*kw + 1];
        }
    }
    g_vbf[i] = packbf(lo, hi);
}

// ---------------------------------------------------------------------------
// TH[r] = T @ W_r (tid < 128)
__device__ void d_thgemm(int oc, int r) {
    int tid = threadIdx.x, wid = tid >> 5, lane = tid & 31;
    int lq = lane >> 2, lr = lane & 3;
    int mw = wid >> 1, nw = wid & 1;

    extern __shared__ uint32_t smu[];
    uint32_t sm_sh = (uint32_t)__cvta_generic_to_shared(smu);
    const uint32_t wsOff = 64*KW*4;

    const uint32_t* wg = g_wbf + ((size_t)r*WNP + oc*104)*XKW;

    uint32_t aOff = (((mw*32 + (lane & 15))*KW + (lane >> 4)*4) << 2);
    int rw = lane & 7, grp = lane >> 3;
    uint32_t bRow = (grp >> 1)*8 + rw;
    uint32_t bWof = (grp & 1)*4;
    uint32_t rw2 = lane & 7, bW2 = ((lane >> 3) & 1)*4;
    int nBase = nw ? 56 : 0;

    float acc[2][7][4];
    #pragma unroll
    for (int t = 0; t < 2; ++t)
        #pragma unroll
        for (int j = 0; j < 7; ++j)
            #pragma unroll
            for (int q = 0; q < 4; ++q) acc[t][j][q] = 0.f;

    auto stage = [&](int kc, int bsel) {
        uint32_t base = sm_sh + bsel*(TBUF*4);
        #pragma unroll 1
        for (int i = tid; i < 1344; i += 128) {
            int row = i >> 3, q = i & 7;
            if (row < 64) {
                cpa16(base + ((row*KW + q*4) << 2), g_tbf + row*XKW + kc*32 + q*4);
            } else {
                int n = row - 64;
                cpa16(base + wsOff + ((n*KW + q*4) << 2),
                      wg + (size_t)n*XKW + kc*32 + q*4);
            }
        }
        CP_COMMIT();
    };

    stage(0, 0);
    for (int kc = 0; kc < 5; ++kc) {
        int bsel = kc & 1;
        if (kc < 4) { stage(kc + 1, bsel ^ 1); CP_WAIT(1); }
        else        { CP_WAIT(0); }
        __syncthreads();
        uint32_t base = sm_sh + bsel*(TBUF*4);
        #pragma unroll
        for (int ks = 0; ks < 4; ++ks) {
            uint32_t A[2][4];
            #pragma unroll
            for (int t = 0; t < 2; ++t)
                LDSM4(A[t][0], A[t][1], A[t][2], A[t][3],
                      base + aOff + (uint32_t)t*(16*KW*4) + ks*32);
            #pragma unroll
            for (int p = 0; p < 3; ++p) {
                uint32_t b0, b1, b2, b3;
                LDSM4(b0, b1, b2, b3,
                      base + wsOff + ((((nBase + p*16 + bRow)*KW + bWof) << 2) + ks*32));
                #pragma unroll
                for (int t = 0; t < 2; ++t) {
                    MMA_BF16(acc[t][2*p],   A[t][0],A[t][1],A[t][2],A[t][3], b0, b1);
                    MMA_BF16(acc[t][2*p+1], A[t][0],A[t][1],A[t][2],A[t][3], b2, b3);
                }
            }
            if (nw == 0) {
                uint32_t c0, c1;
                LDSM2(c0, c1, base + wsOff + ((((48 + rw2)*KW + bW2) << 2) + ks*32));
                #pragma unroll
                for (int t = 0; t < 2; ++t)
                    MMA_BF16(acc[t][6], A[t][0],A[t][1],A[t][2],A[t][3], c0, c1);
            }
        }
        __syncthreads();
    }
    int nt0 = nw*7, nts = nw ? 6 : 7;
    #pragma unroll
    for (int t = 0; t < 2; ++t) {
        int row = mw*32 + t*16 + lq;
        #pragma unroll
        for (int j = 0; j < 7; ++j) {
            if (j < nts) {
                int c = (nt0 + j)*8 + lr*2;
                size_t b0i = ((size_t)r*WNP + oc*104 + c)*64;
                size_t b1i = ((size_t)r*WNP + oc*104 + c + 1)*64;
                g_tht[b0i + row]     = (unsigned short)packbf(acc[t][j][0], 0.f);
                g_tht[b1i + row]     = (unsigned short)packbf(acc[t][j][1], 0.f);
                g_tht[b0i + row + 8] = (unsigned short)packbf(acc[t][j][2], 0.f);
                g_tht[b1i + row + 8] = (unsigned short)packbf(acc[t][j][3], 0.f);
            }
        }
    }
}

// ---------------------------------------------------------------------------
__device__ void d_ugemm(int l, int bp) {
    int tid = threadIdx.x, wid = tid >> 5, lane = tid & 31;
    int lq = lane >> 2, lr = lane & 3;
    int mw = wid >> 1, nw = wid & 1;

    extern __shared__ uint32_t smu[];
    uint32_t sm_sh = (uint32_t)__cvta_generic_to_shared(smu);
    const uint32_t vOff = 192*KW*4;

    const uint32_t* xg = g_xbf + (size_t)(bp*192)*XKW;
    const uint32_t* vg = g_vbf + (size_t)(l*48)*XKW;

    uint32_t aOff = (((mw*48 + (lane & 15))*KW + (lane >> 4)*4) << 2);
    int rw = lane & 7, grp = lane >> 3;
    uint32_t bRow = (grp >> 1)*8 + rw;
    uint32_t bWof = (grp & 1)*4;
    uint32_t rw2 = lane & 7, bW2 = ((lane >> 3) & 1)*4;
    int nBase = nw*24;

    float acc[3][3][4];
    #pragma unroll
    for (int t = 0; t < 3; ++t)
        #pragma unroll
        for (int j = 0; j < 3; ++j)
            #pragma unroll
            for (int q = 0; q < 4; ++q) acc[t][j][q] = 0.f;

    auto stage = [&](int kc, int bsel) {
        uint32_t base = sm_sh + bsel*(UBUF*4);
        #pragma unroll 1
        for (int i = tid; i < 1920; i += 256) {
            uint32_t dst; const uint32_t* src;
            int row = i >> 3, q = i & 7;
            if (row < 192) {
                dst = base + ((row*KW + q*4) << 2);
                src = xg + (size_t)row*XKW + kc*32 + q*4;
            } else {
                int vr = row - 192;
                dst = base + vOff + ((vr*KW + q*4) << 2);
                src = vg + (size_t)vr*XKW + kc*32 + q*4;
            }
            cpa16(dst, src);
        }
        CP_COMMIT();
    };

    stage(0, 0);
    for (int kc = 0; kc < 5; ++kc) {
        int bsel = kc & 1;
        if (kc < 4) { stage(kc + 1, bsel ^ 1); CP_WAIT(1); }
        else        { CP_WAIT(0); }
        __syncthreads();
        uint32_t base = sm_sh + bsel*(UBUF*4);
        #pragma unroll
        for (int ks = 0; ks < 4; ++ks) {
            uint32_t A[3][4];
            #pragma unroll
            for (int t = 0; t < 3; ++t)
                LDSM4(A[t][0], A[t][1], A[t][2], A[t][3],
                      base + aOff + (uint32_t)t*(16*KW*4) + ks*32);
            uint32_t b0, b1, b2, b3;
            LDSM4(b0, b1, b2, b3,
                  base + vOff + ((((nBase + bRow)*KW + bWof) << 2) + ks*32));
            uint32_t c0, c1;
            LDSM2(c0, c1, base + vOff + ((((nBase + 16 + rw2)*KW + bW2) << 2) + ks*32));
            #pragma unroll
            for (int t = 0; t < 3; ++t) {
                MMA_BF16(acc[t][0], A[t][0],A[t][1],A[t][2],A[t][3], b0, b1);
                MMA_BF16(acc[t][1], A[t][0],A[t][1],A[t][2],A[t][3], b2, b3);
                MMA_BF16(acc[t][2], A[t][0],A[t][1],A[t][2],A[t][3], c0, c1);
            }
        }
        __syncthreads();
    }
    #pragma unroll
    for (int t = 0; t < 3; ++t) {
        int row0 = mw*48 + t*16 + lq;
        #pragma unroll
        for (int j = 0; j < 3; ++j) {
            int c = nBase + j*8 + lr*2;
            #pragma unroll
            for (int h = 0; h < 2; ++h) {
                int row = row0 + h*8;
                int b = bp*2 + (row >= 96), s = row & 95;
                if (c < Rr)     g_u[(b*Rr + c)*Ss + s]     = acc[t][j][2*h];
                if (c + 1 < Rr) g_u[(b*Rr + c + 1)*Ss + s] = acc[t][j][2*h + 1];
            }
        }
    }
}

// ---------------------------------------------------------------------------
// Fused scores + softmax; l=1 also emits A'; l=0 writes wd to global.
__device__ void d_sap(const float* __restrict__ adj, int b, int sq, int l) {
    int s0 = sq*SQ;
    __shared__ float usm[Rr][Ss];
    __shared__ float scs[Rr][SQ];
    __shared__ float dns[Rr][SQ];
    __shared__ float wds[Rr][SQ];
    int tid = threadIdx.x;
    for (int i = tid; i < Rr*Ss; i += 256) usm[i/Ss][i%Ss] = g_u[b*Rr*Ss + i];
    __syncthreads();
    for (int i = tid; i < Rr*SQ; i += 256) {
        int r = i / SQ, t = i % SQ;
        const float4* ar = (const float4*)(adj + (((size_t)b*Rr + r)*Ss + s0 + t)*Ss);
        const float* u = usm[r];
        float d = 0.f, sr = 0.f;
        #pragma unroll 6
        for (int j = 0; j < Ss/4; ++j) {
            float4 av = ar[j];
            d  += av.x + av.y + av.z + av.w;
            sr += av.x*u[4*j] + av.y*u[4*j+1] + av.z*u[4*j+2] + av.w*u[4*j+3];
        }
        float ds = (d == 0.f) ? 1.f : d;
        scs[r][t] = sr/ds;
        dns[r][t] = ds;
    }
    __syncthreads();
    if (tid < SQ) {
        int t = tid;
        float mx = -1e30f;
        for (int r = 0; r < Rr; ++r) mx = fmaxf(mx, scs[r][t]);
        float Z = 0.f;
        for (int r = 0; r < Rr; ++r) Z += expf(scs[r][t] - mx);
        for (int r = 0; r < Rr; ++r) {
            float w = expf(scs[r][t] - mx) / (Z * dns[r][t]);
            wds[r][t] = w;
            if (l == 0) g_wd[(b*Rr + r)*Ss + s0 + t] = w;
        }
    }
    __syncthreads();
    if (l == 1) {
        for (int i = tid; i < Rr*SQ*(Ss/4); i += 256) {
            int r = i / (SQ*(Ss/4)), rem = i % (SQ*(Ss/4));
            int t = rem / (Ss/4), q = rem % (Ss/4);
            const float4* ar = (const float4*)(adj + (((size_t)b*Rr + r)*Ss + s0 + t)*Ss);
            float4 av = ar[q];
            float w = wds[r][t];
            uint32_t* out = g_apbf + ((size_t)(b*Rr + r))*Ss*48 + (size_t)(s0 + t)*48;
            out[2*q]     = packbf(av.x*w, av.y*w);
            out[2*q + 1] = packbf(av.z*w, av.w*w);
        }
    }
}

// ---------------------------------------------------------------------------
// Ac build: Ac[s][p] = wd[s] * sum_{t: tag[t]=p} adj[s][t]   — grid (b, r)
__global__ void __launch_bounds__(128)
k_acb(const float* __restrict__ adj) {
    int b = blockIdx.x, r = blockIdx.y;
    __shared__ float adjsm[96][97];
    __shared__ unsigned short permS[96];
    __shared__ unsigned short segsS[65];
    __shared__ float wdS[96];
    int tid = threadIdx.x;
    if (tid < 96) {
        permS[tid] = g_perm[b][tid];
        wdS[tid] = g_wd[(b*Rr + r)*Ss + tid];
    }
    if (tid < 65) segsS[tid] = g_segs[b][tid];
    const float4* ar = (const float4*)(adj + ((size_t)b*Rr + r)*Ss*Ss);
    #pragma unroll 4
    for (int i = tid; i < 96*24; i += 128) {
        int s = i / 24, q = i % 24;
        float4 v = ar[i];
        adjsm[s][q*4]   = v.x; adjsm[s][q*4+1] = v.y;
        adjsm[s][q*4+2] = v.z; adjsm[s][q*4+3] = v.w;
    }
    __syncthreads();
    uint32_t* out = g_acbf + ((size_t)(b*Rr + r))*Ss*32;
    #pragma unroll 4
    for (int i = tid; i < 96*32; i += 128) {
        int s = i >> 5, p2 = i & 31;
        float w = wdS[s];
        int p0 = 2*p2;
        float a0 = 0.f, a1 = 0.f;
        for (int j = segsS[p0]; j < segsS[p0+1]; ++j) a0 += adjsm[s][permS[j]];
        for (int j = segsS[p0+1]; j < segsS[p0+2]; ++j) a1 += adjsm[s][permS[j]];
        out[s*32 + p2] = packbf(a0*w, a1*w);
    }
}

// ---------------------------------------------------------------------------
__device__ void d_hidgemm(int l, int bp, int oc, int r) {
    int tid = threadIdx.x, wid = tid >> 5, lane = tid & 31;
    int lq = lane >> 2, lr = lane & 3;
    int mw = wid >> 1, nw = wid & 1;

    extern __shared__ uint32_t smu[];
    uint32_t sm_sh = (uint32_t)__cvta_generic_to_shared(smu);

    const uint32_t* xg = g_xbf + (size_t)(bp*2)*Ss*XKW;
    const uint32_t* wg = g_wbf + ((size_t)(l*Rr + r)*WNP + oc*OCW)*XKW;

    const uint32_t wsOff = 192*KW*4;

    uint32_t aOff = (((mw*48 + (lane & 15))*KW + (lane >> 4)*4) << 2);
    int rw = lane & 7, grp = lane >> 3;
    uint32_t bRow = (grp >> 1)*8 + rw;
    uint32_t bWof = (grp & 1)*4;
    uint32_t rw2 = lane & 7, bW2 = ((lane >> 3) & 1)*4;
    int nBase = nw ? 56 : 0;

    float acc[3][7][4];
    #pragma unroll
    for (int t = 0; t < 3; ++t)
        #pragma unroll
        for (int j = 0; j < 7; ++j)
            #pragma unroll
            for (int q = 0; q < 4; ++q) acc[t][j][q] = 0.f;

    auto stage = [&](int kc, int bsel) {
        uint32_t base = sm_sh + bsel*(ABUF2*4);
        #pragma unroll 1
        for (int i = tid; i < 2368; i += 256) {
            uint32_t dst; const uint32_t* src;
            if (i < 1536) {
                int row = i >> 3, q = i & 7;
                dst = base + ((row*KW + q*4) << 2);
                src = xg + row*XKW + kc*32 + q*4;
            } else {
                int j = i - 1536;
                int row = j >> 3, q = j & 7;
                dst = base + wsOff + ((row*KW + q*4) << 2);
                src = wg + (size_t)row*XKW + kc*32 + q*4;
            }
            cpa16(dst, src);
        }
        CP_COMMIT();
    };

    stage(0, 0);
    for (int kc = 0; kc < 5; ++kc) {
        int bsel = kc & 1;
        if (kc < 4) { stage(kc + 1, bsel ^ 1); CP_WAIT(1); }
        else        { CP_WAIT(0); }
        __syncthreads();
        uint32_t base = sm_sh + bsel*(ABUF2*4);
        #pragma unroll
        for (int ks = 0; ks < 4; ++ks) {
            uint32_t A[3][4];
            #pragma unroll
            for (int t = 0; t < 3; ++t)
                LDSM4(A[t][0], A[t][1], A[t][2], A[t][3],
                      base + aOff + (uint32_t)t*(16*KW*4) + ks*32);
            #pragma unroll
            for (int p = 0; p < 3; ++p) {
                uint32_t b0, b1, b2, b3;
                LDSM4(b0, b1, b2, b3,
                      base + wsOff + ((((nBase + p*16 + bRow)*KW + bWof) << 2) + ks*32));
                #pragma unroll
                for (int t = 0; t < 3; ++t) {
                    MMA_BF16(acc[t][2*p],   A[t][0],A[t][1],A[t][2],A[t][3], b0, b1);
                    MMA_BF16(acc[t][2*p+1], A[t][0],A[t][1],A[t][2],A[t][3], b2, b3);
                }
            }
            if (nw == 0) {
                uint32_t c0, c1;
                LDSM2(c0, c1, base + wsOff + ((((48 + rw2)*KW + bW2) << 2) + ks*32));
                #pragma unroll
                for (int t = 0; t < 3; ++t)
                    MMA_BF16(acc[t][6], A[t][0],A[t][1],A[t][2],A[t][3], c0, c1);
            }
        }
        __syncthreads();
    }
    {
        int b_local = mw >> 1;
        int rloc = mw*48 - b_local*96;
        __nv_bfloat16* hidB = (__nv_bfloat16*)(smu + b_local*ABUF2);
        int nt0 = nw*7, nts = nw ? 6 : 7;
        #pragma unroll
        for (int t = 0; t < 3; ++t) {
            int row = rloc + t*16 + lq;
            #pragma unroll
            for (int j = 0; j < 7; ++j) {
                if (j < nts) {
                    int c = (nt0 + j)*8 + lr*2;
                    hidB[(size_t)c*(2*TW) + row]         = __float2bfloat16_rn(acc[t][j][0]);
                    hidB[(size_t)(c+1)*(2*TW) + row]     = __float2bfloat16_rn(acc[t][j][1]);
                    hidB[(size_t)c*(2*TW) + row + 8]     = __float2bfloat16_rn(acc[t][j][2]);
                    hidB[(size_t)(c+1)*(2*TW) + row + 8] = __float2bfloat16_rn(acc[t][j][3]);
                }
            }
        }
    }
    __syncthreads();
    #pragma unroll
    for (int bi = 0; bi < 2; ++bi) {
        uint32_t* hg = g_hid + ((size_t)(r*Bb + bp*2 + bi)*3 + oc)*HCH;
        const uint32_t* src = smu + bi*ABUF2;
        #pragma unroll 4
        for (int i = tid; i < HCH; i += 256) hg[i] = src[i];
    }
}

// ---------------------------------------------------------------------------
// Merged launch kernels
__global__ void __launch_bounds__(320)
k_pre1(const float* __restrict__ posemb, const float* __restrict__ linW,
       const float* __restrict__ linb, const float* __restrict__ text,
       const float* __restrict__ rgcnW, const float* __restrict__ scoreW,
       const void* tags, const void* masks, int ntag, int nmask) {
    int bx = blockIdx.x;
    if (bx < 4100) {
        if (threadIdx.x >= 256) return;
        d_wcvt(rgcnW, scoreW, bx % 82, (bx/82) % 10, bx/820);
    } else {
        d_detpost(posemb, linW, linb, text, tags, masks, ntag, nmask, bx - 4100);
    }
}

__global__ void k_pre2(const void* tags) {
    int bx = blockIdx.x;
    if (bx < 1960) d_gather(tags, bx*256 + threadIdx.x);
    else           d_vsum((bx - 1960)*256 + threadIdx.x);
}

__global__ void __launch_bounds__(256)
k_pre3() {
    int bx = blockIdx.x;
    if (bx < 123) {
        if (threadIdx.x >= 128) return;
        d_thgemm(bx % 3, bx / 3);
    } else {
        d_ugemm(0, bx - 123);
    }
}

__global__ void __launch_bounds__(256)
k_sap(const float* __restrict__ adj, int l) {
    d_sap(adj, blockIdx.x, blockIdx.y, l);
}

__global__ void __launch_bounds__(256, 2)
k_l1a() {
    int bx = blockIdx.x;
    if (bx < 1968) d_hidgemm(1, bx % 16, (bx/16) % 3, bx/48);
    else           d_ugemm(1, bx - 1968);
}

// ---------------------------------------------------------------------------
// GEMM B dual-mode:
//  l=1: part += A'(96xK96) @ hid(104xK96)   (strides TW)
//  l=0: part += Ac(96xK64) @ TH(104xK64)    (strides KW), TH shared across b
__global__ void __launch_bounds__(192)
k_pass2b(int l) {
    int b = blockIdx.x, oc = blockIdx.y, g = blockIdx.z;
    int tid = threadIdx.x, wid = tid >> 5, lane = tid & 31;
    int lq = lane >> 2, lr = lane & 3;
    int mw = wid % 3, nw = wid / 3;
    int r0 = g*14, nr = (g == 2) ? 13 : 14;

    extern __shared__ uint32_t smu[];
    uint32_t sm_sh = (uint32_t)__cvta_generic_to_shared(smu);

    const int AST = l ? TW : KW;
    const uint32_t bReg = l ? (96*TW*4) : (96*KW*4);
    const int KS = l ? 6 : 4;

    uint32_t aOff = (((mw*32 + (lane & 15))*AST + (lane >> 4)*4) << 2);
    int rw = lane & 7, grp = lane >> 3;
    uint32_t bRow = (grp >> 1)*8 + rw;
    uint32_t bWof = (grp & 1)*4;
    uint32_t rw2 = lane & 7, bW2 = ((lane >> 3) & 1)*4;
    int nBase = nw ? 56 : 0;

    float acc[2][7][4];
    #pragma unroll
    for (int t = 0; t < 2; ++t)
        #pragma unroll
        for (int j = 0; j < 7; ++j)
            #pragma unroll
            for (int q = 0; q < 4; ++q) acc[t][j][q] = 0.f;

    auto stage = [&](int rr, int bsel) {
        int r = r0 + rr;
        uint32_t base = sm_sh + bsel*(BBUF*4);
        if (l) {
            const uint32_t* ag = g_apbf + ((size_t)(b*Rr + r))*Ss*48;
            const uint32_t* hg = g_hid + ((size_t)(r*Bb + b)*3 + oc)*HCH;
            #pragma unroll 1
            for (int i = tid; i < 2504; i += 192) {
                uint32_t dst; const uint32_t* src;
                if (i < 1152) {
                    int row = i / 12, q = i % 12;
                    dst = base + ((row*TW + q*4) << 2);
                    src = ag + row*48 + q*4;
                } else {
                    int j = i - 1152;
                    dst = base + bReg + (j << 4);
                    src = hg + j*4;
                }
                cpa16(dst, src);
            }
        } else {
            const uint32_t* ag = g_acbf + ((size_t)(b*Rr + r))*Ss*32;
            const uint32_t* tg = (const uint32_t*)(g_tht + ((size_t)r*WNP + oc*OCW)*64);
            #pragma unroll 1
            for (int i = tid; i < 1600; i += 192) {
                uint32_t dst; const uint32_t* src;
                if (i < 768) {
                    int row = i >> 3, q = i & 7;
                    dst = base + ((row*KW + q*4) << 2);
                    src = ag + row*32 + q*4;
                } else {
                    int j = i - 768;
                    int row = j >> 3, q = j & 7;
                    dst = base + bReg + ((row*KW + q*4) << 2);
                    src = tg + row*32 + q*4;
                }
                cpa16(dst, src);
            }
        }
        CP_COMMIT();
    };

    stage(0, 0);
    for (int rr = 0; rr < nr; ++rr) {
        int bsel = rr & 1;
        if (rr + 1 < nr) { stage(rr + 1, bsel ^ 1); CP_WAIT(1); }
        else             { CP_WAIT(0); }
        __syncthreads();
        uint32_t base = sm_sh + bsel*(BBUF*4);
        #pragma unroll 2
        for (int ks = 0; ks < KS; ++ks) {
            uint32_t A[2][4];
            #pragma unroll
            for (int t = 0; t < 2; ++t)
                LDSM4(A[t][0], A[t][1], A[t][2], A[t][3],
                      base + aOff + (uint32_t)t*(16*AST*4) + ks*32);
            #pragma unroll
            for (int p = 0; p < 3; ++p) {
                uint32_t b0, b1, b2, b3;
                LDSM4(b0, b1, b2, b3,
                      base + bReg + ((((nBase + p*16 + bRow)*AST + bWof) << 2) + ks*32));
                #pragma unroll
                for (int t = 0; t < 2; ++t) {
                    MMA_BF16(acc[t][2*p],   A[t][0],A[t][1],A[t][2],A[t][3], b0, b1);
                    MMA_BF16(acc[t][2*p+1], A[t][0],A[t][1],A[t][2],A[t][3], b2, b3);
                }
            }
            if (nw == 0) {
                uint32_t c0, c1;
                LDSM2(c0, c1, base + bReg + ((((48 + rw2)*AST + bW2) << 2) + ks*32));
                #pragma unroll
                for (int t = 0; t < 2; ++t)
                    MMA_BF16(acc[t][6], A[t][0],A[t][1],A[t][2],A[t][3], c0, c1);
            }
        }
        __syncthreads();
    }

    float* pp = g_part + ((size_t)(b*NG + g))*Ss*Hh;
    int o0 = oc*OCW;
    int nt0 = nw*7, nts = nw ? 6 : 7;
    #pragma unroll
    for (int t = 0; t < 2; ++t) {
        int row = mw*32 + t*16 + lq;
        #pragma unroll
        for (int j = 0; j < 7; ++j) {
            if (j < nts) {
                int c = (nt0 + j)*8 + lr*2;
                if (c < OCW) {
                    pp[row*Hh + o0 + c]         = acc[t][j][0];
                    pp[row*Hh + o0 + c + 1]     = acc[t][j][1];
                    pp[(row+8)*Hh + o0 + c]     = acc[t][j][2];
                    pp[(row+8)*Hh + o0 + c + 1] = acc[t][j][3];
                }
            }
        }
    }
}

// x_out = relu(sum over groups): l=0 -> packed bf16x2; l=1 -> fp32 for pooling
__global__ void k_reduce(int l) {
    int idx = blockIdx.x*blockDim.x + threadIdx.x;
    if (l == 0) {
        if (idx >= Bb*Ss*XKW) return;
        int kw = idx % XKW, bs = idx / XKW;
        if (kw >= Hh/2) return;
        int b = bs / Ss;
        size_t inner = (size_t)(bs % Ss)*Hh + 2*kw;
        float a0 = 0.f, a1 = 0.f;
        #pragma unroll
        for (int g = 0; g < NG; ++g) {
            const float* pp = g_part + ((size_t)(b*NG + g))*Ss*Hh + inner;
            a0 += pp[0]; a1 += pp[1];
        }
        g_xbf[idx] = packbf(fmaxf(a0, 0.f), fmaxf(a1, 0.f));
    } else {
        if (idx >= Bb*Ss*(Hh/2)) return;
        int kw = idx % (Hh/2), bs = idx / (Hh/2);
        int b = bs / Ss;
        size_t inner = (size_t)(bs % Ss)*Hh + 2*kw;
        float a0 = 0.f, a1 = 0.f;
        #pragma unroll
        for (int g = 0; g < NG; ++g) {
            const float* pp = g_part + ((size_t)(b*NG + g))*Ss*Hh + inner;
            a0 += pp[0]; a1 += pp[1];
        }
        *(float2*)&g_x0[(size_t)bs*Hh + 2*kw] =
            make_float2(fmaxf(a0, 0.f), fmaxf(a1, 0.f));
    }
}

// ---------------------------------------------------------------------------
__global__ void k_final(const float* __restrict__ dW, const float* __restrict__ db,
                        float* __restrict__ out) {
    int b = blockIdx.x, tid = threadIdx.x;  // 320
    __shared__ float red0[320], red1[320], red2[320];
    float p0 = 0.f, p1 = 0.f, p2 = 0.f;
    if (tid < Hh) {
        float a = 0.f;
        for (int s = 0; s < Ss; ++s) a += g_x0[((size_t)b*Ss + s)*Hh + tid];
        float hg = a / g_rlen[b];
        float hc = g_hcmean[b*Hh + tid];
        p0 = hg*dW[tid*NLAB + 0] + hc*dW[(Hh + tid)*NLAB + 0];
        p1 = hg*dW[tid*NLAB + 1] + hc*dW[(Hh + tid)*NLAB + 1];
        p2 = hg*dW[tid*NLAB + 2] + hc*dW[(Hh + tid)*NLAB + 2];
    }
    red0[tid] = p0; red1[tid] = p1; red2[tid] = p2;
    __syncthreads();
    for (int st = 160; st >= 5; st >>= 1) {
        if (tid < st) {
            red0[tid] += red0[tid + st];
            red1[tid] += red1[tid + st];
            red2[tid] += red2[tid + st];
        }
        __syncthreads();
    }
    if (tid < NLAB) {
        float* rn = (tid == 0) ? red0 : (tid == 1) ? red1 : red2;
        float a = db[tid];
        #pragma unroll
        for (int i = 0; i < 5; ++i) a += rn[i];
        out[b*NLAB + tid] = a;
    }
}

// ---------------------------------------------------------------------------
extern "C" void kernel_launch(void* const* d_in, const int* in_sizes, int n_in,
                              void* d_out, int out_size) {
    const float* text   = (const float*)d_in[0];
    const void*  masks  = d_in[1];
    const void*  tags   = d_in[2];
    const float* adj    = (const float*)d_in[3];
    const float* posemb = (const float*)d_in[4];
    const float* linW   = (const float*)d_in[5];
    const float* linb   = (const float*)d_in[6];
    const float* rgcnW  = (const float*)d_in[7];
    const float* scoreW = (const float*)d_in[8];
    // d_in[9] = score_b: softmax over relations is invariant to it — unused
    const float* dW     = (const float*)d_in[10];
    const float* db     = (const float*)d_in[11];
    float*       out    = (float*)d_out;

    const int SMEM_P3 = 2*UBUF*4;    // 69120
    const int SMEM_L1 = 2*ABUF2*4;   // 85248
    const int SMEM_B  = 2*BBUF*4;    // 83200
    cudaFuncSetAttribute(k_pre3,  cudaFuncAttributeMaxDynamicSharedMemorySize, SMEM_P3);
    cudaFuncSetAttribute(k_l1a,   cudaFuncAttributeMaxDynamicSharedMemorySize, SMEM_L1);
    cudaFuncSetAttribute(k_pass2b, cudaFuncAttributeMaxDynamicSharedMemorySize, SMEM_B);

    k_pre1<<<4100 + NPOS + 2 + Bb, 320>>>(posemb, linW, linb, text, rgcnW, scoreW,
                                          tags, masks, in_sizes[2], in_sizes[1]);
    k_pre2<<<1960 + 60, 256>>>(tags);
    k_pre3<<<123 + 16, 256, SMEM_P3>>>();
    k_sap<<<dim3(Bb, 4), 256>>>(adj, 0);            // ncu capture slot (idx 3)
    k_acb<<<dim3(Bb, Rr), 128>>>(adj);
    k_pass2b<<<dim3(Bb, 3, NG), 192, SMEM_B>>>(0);
    k_reduce<<<(Bb*Ss*XKW + 255)/256, 256>>>(0);
    k_l1a<<<1968 + 16, 256, SMEM_L1>>>();
    k_sap<<<dim3(Bb, 4), 256>>>(adj, 1);
    k_pass2b<<<dim3(Bb, 3, NG), 192, SMEM_B>>>(1);
    k_reduce<<<(Bb*Ss*XKW + 255)/256, 256>>>(1);
    k_final<<<Bb, 320>>>(dW, db, out);
}

// round 17
// speedup vs baseline: 1.2547x; 1.0699x over previous
#include <cuda_runtime.h>
#include <cuda_bf16.h>
#include <math.h>
#include <stdint.h>

// Problem constants
#define Bb 32
#define Ll 128
#define Ss 96
#define Ee 768
#define Hh 300
#define Rr 41
#define NPOS 50
#define NLAB 3
#define NG 3        // relation groups (14,14,13)
#define OCW 100

// packed layouts
#define XKW 160
#define WNP 312
#define KW  36
#define TW  52
#define HCH 5408
#define ABUF2 (192*KW + 104*KW)   // 10656 words
#define TBUF  (64*KW + 104*KW)    // 6048 words
#define UBUF  (192*KW + 48*KW)    // 8640 words
#define BBUF 10400

// Scratch (device globals — no allocations allowed)
__device__ float    g_hcmean[Bb*Hh];
__device__ float    g_T[NPOS*Hh];
__device__ float    g_x0[Bb*Ss*Hh];
__device__ float    g_rlen[Bb];
__device__ float    g_vpart[2*Rr*10*Hh];
__device__ float    g_u[Bb*Rr*Ss];
__device__ float    g_sc[Bb*Rr*Ss];
__device__ float    g_den[Bb*Rr*Ss];
__device__ float    g_part[(size_t)Bb*NG*Ss*Hh];
__device__ int      g_tag64;
__device__ int      g_mask64;
__device__ unsigned short g_perm[Bb][96];
__device__ unsigned short g_segs[Bb][65];
__device__ uint32_t g_xbf[Bb*Ss*XKW];
__device__ uint32_t g_tbf[64*XKW];
__device__ unsigned short g_tht[(size_t)Rr*WNP*64];
__device__ uint32_t g_vbf[2*48*XKW];
__device__ uint32_t g_wbf[(size_t)2*Rr*WNP*XKW];
__device__ uint32_t g_hid[(size_t)Rr*Bb*3*HCH];
__device__ uint32_t g_apbf[(size_t)Bb*Rr*Ss*48];
__device__ uint32_t g_acbf[(size_t)Bb*Rr*Ss*32];

__device__ __forceinline__ uint32_t packbf(float lo, float hi) {
    uint32_t d;
    asm("cvt.rn.bf16x2.f32 %0, %1, %2;" : "=r"(d) : "f"(hi), "f"(lo));
    return d;
}

__device__ __forceinline__ int load_tag(const void* tags, int idx) {
    int t;
    if (g_tag64) t = (int)((const long long*)tags)[idx];
    else         t = ((const int*)tags)[idx];
    return (t < 0) ? 0 : (t >= NPOS ? NPOS-1 : t);
}

__device__ __forceinline__ void cpa16(uint32_t dst_sh, const void* src) {
    asm volatile("cp.async.ca.shared.global [%0], [%1], 16;" :: "r"(dst_sh), "l"(src));
}
#define CP_COMMIT() asm volatile("cp.async.commit_group;")
#define CP_WAIT(n)  asm volatile("cp.async.wait_group %0;" :: "n"(n))

#define MMA_BF16(c, a0,a1,a2,a3, b0,b1) \
    asm volatile("mma.sync.aligned.m16n8k16.row.col.f32.bf16.bf16.f32 " \
        "{%0,%1,%2,%3}, {%4,%5,%6,%7}, {%8,%9}, {%0,%1,%2,%3};" \
        : "+f"((c)[0]), "+f"((c)[1]), "+f"((c)[2]), "+f"((c)[3]) \
        : "r"(a0), "r"(a1), "r"(a2), "r"(a3), "r"(b0), "r"(b1))

#define LDSM4(r0,r1,r2,r3, addr) \
    asm volatile("ldmatrix.sync.aligned.m8n8.x4.shared.b16 {%0,%1,%2,%3}, [%4];" \
        : "=r"(r0), "=r"(r1), "=r"(r2), "=r"(r3) : "r"(addr))

#define LDSM2(r0,r1, addr) \
    asm volatile("ldmatrix.sync.aligned.m8n8.x2.shared.b16 {%0,%1}, [%2];" \
        : "=r"(r0), "=r"(r1) : "r"(addr))

// ---------------------------------------------------------------------------
__device__ void d_detpost(const float* __restrict__ posemb,
                          const float* __restrict__ linW,
                          const float* __restrict__ linb,
                          const float* __restrict__ text,
                          const void* tags, const void* masks,
                          int ntag, int nmask, int bid) {
    int tid = threadIdx.x;  // 320
    if (bid < NPOS) {
        int p = bid;
        __shared__ float pe[Ee];
        for (int e = tid; e < Ee; e += 320) pe[e] = posemb[p*Ee + e];
        __syncthreads();
        if (tid < Hh) {
            float s0=0.f, s1=0.f, s2=0.f, s3=0.f;
            #pragma unroll 2
            for (int e = 0; e < Ee; e += 4) {
                s0 += pe[e  ]*linW[(e  )*Hh + tid];
                s1 += pe[e+1]*linW[(e+1)*Hh + tid];
                s2 += pe[e+2]*linW[(e+2)*Hh + tid];
                s3 += pe[e+3]*linW[(e+3)*Hh + tid];
            }
            g_T[p*Hh + tid] = linb[tid] + (s0+s1) + (s2+s3);
        }
    } else if (bid == NPOS) {
        __shared__ int okt, okm;
        if (tid == 0) { okt = 1; okm = 1; }
        __syncthreads();
        const long long* t64 = (const long long*)tags;
        for (int i = tid; i < ntag/2; i += 320) {
            long long v = t64[i];
            if (v < 0 || v >= NPOS) okt = 0;
        }
        const long long* m64 = (const long long*)masks;
        for (int i = tid; i < nmask/2; i += 320) {
            long long v = m64[i];
            if (v < 0 || v > 1) okm = 0;
        }
        __syncthreads();
        if (tid == 0) { g_tag64 = okt; g_mask64 = okm; }
    } else if (bid == NPOS + 1) {
        __shared__ int okt2;
        __shared__ int cnt[Bb];
        if (tid == 0) okt2 = 1;
        if (tid < Bb) cnt[tid] = 0;
        __syncthreads();
        const long long* t64 = (const long long*)tags;
        for (int i = tid; i < ntag/2; i += 320) {
            long long v = t64[i];
            if (v < 0 || v >= NPOS) okt2 = 0;
        }
        __syncthreads();
        int is64 = okt2;
        for (int i = tid; i < Bb*Ss; i += 320) {
            int t = is64 ? (int)((const long long*)tags)[i] : ((const int*)tags)[i];
            if (t != 0) atomicAdd(&cnt[i/Ss], 1);
        }
        __syncthreads();
        if (tid < Bb) g_rlen[tid] = (float)cnt[tid];
        // counting-sort permutation of t by tag, per batch (one thread per b)
        if (tid < Bb) {
            int b = tid;
            unsigned short cbin[64];
            #pragma unroll
            for (int p = 0; p < 64; ++p) cbin[p] = 0;
            int tg[96];
            for (int t = 0; t < Ss; ++t) {
                int v = is64 ? (int)((const long long*)tags)[b*Ss + t]
                             : ((const int*)tags)[b*Ss + t];
                v = (v < 0) ? 0 : (v >= NPOS ? NPOS-1 : v);
                tg[t] = v;
                cbin[v]++;
            }
            int acc = 0;
            unsigned short start[64];
            #pragma unroll
            for (int p = 0; p < 64; ++p) {
                start[p] = (unsigned short)acc;
                g_segs[b][p] = (unsigned short)acc;
                acc += cbin[p];
            }
            g_segs[b][64] = (unsigned short)acc;  // == 96
            for (int t = 0; t < Ss; ++t)
                g_perm[b][start[tg[t]]++] = (unsigned short)t;
        }
    } else {
        int b = bid - (NPOS + 2);
        __shared__ float ts[Ee];
        __shared__ float msum[128];
        __shared__ int okm2;
        if (tid == 0) okm2 = 1;
        __syncthreads();
        const long long* m64 = (const long long*)masks;
        for (int i = tid; i < nmask/2; i += 320) {
            long long v = m64[i];
            if (v < 0 || v > 1) okm2 = 0;
        }
        for (int e = tid; e < Ee; e += 320) {
            const float* p = text + (size_t)b*Ll*Ee + e;
            float s0=0.f, s1=0.f, s2=0.f, s3=0.f;
            #pragma unroll 4
            for (int l = 0; l < Ll; l += 4) {
                s0 += p[(size_t)(l  )*Ee];
                s1 += p[(size_t)(l+1)*Ee];
                s2 += p[(size_t)(l+2)*Ee];
                s3 += p[(size_t)(l+3)*Ee];
            }
            ts[e] = (s0+s1) + (s2+s3);
        }
        __syncthreads();
        if (tid < 128) {
            long long v = okm2 ? ((const long long*)masks)[b*Ll + tid]
                               : (long long)((const int*)masks)[b*Ll + tid];
            msum[tid] = (float)v;
        }
        __syncthreads();
        for (int st = 64; st >= 1; st >>= 1) {
            if (tid < st) msum[tid] += msum[tid + st];
            __syncthreads();
        }
        float el = msum[0];
        if (tid < Hh) {
            float s0=0.f, s1=0.f, s2=0.f, s3=0.f;
            #pragma unroll 2
            for (int e = 0; e < Ee; e += 4) {
                s0 += ts[e  ]*linW[(e  )*Hh + tid];
                s1 += ts[e+1]*linW[(e+1)*Hh + tid];
                s2 += ts[e+2]*linW[(e+2)*Hh + tid];
                s3 += ts[e+3]*linW[(e+3)*Hh + tid];
            }
            float a = (s0+s1) + (s2+s3);
            g_hcmean[b*Hh + tid] = a/el + ((float)Ll/el)*linb[tid];
        }
    }
}

__device__ void d_wcvt(const float* __restrict__ rgcnW,
                       const float* __restrict__ scoreW,
                       int lr_, int ny, int kz) {
    int n0 = ny*32, k0 = kz*64;
    int l = lr_ / Rr;
    __shared__ float sm[64][33];
    __shared__ float swsh[32];
    int tid = threadIdx.x, tx = tid & 31, ty = tid >> 5;
    const float* W = rgcnW + (size_t)lr_*Hh*Hh;
    #pragma unroll
    for (int i = 0; i < 8; ++i) {
        int k = ty + i*8;
        int gk = k0 + k, gn = n0 + tx;
        sm[k][tx] = (gk < Hh && gn < Hh) ? W[(size_t)gk*Hh + gn] : 0.f;
    }
    if (tid < 32) {
        int gn = n0 + tid;
        swsh[tid] = (gn < Hh) ? scoreW[l*Hh + gn] : 0.f;
    }
    __syncthreads();
    uint32_t* out = g_wbf + (size_t)lr_*WNP*XKW;
    #pragma unroll
    for (int i = 0; i < 4; ++i) {
        int idx = i*256 + tid;
        int n = idx >> 5, k2 = idx & 31;
        int gn = n0 + n;
        if (gn < WNP)
            out[(size_t)gn*XKW + kz*32 + k2] = packbf(sm[2*k2][n], sm[2*k2+1][n]);
    }
    {
        int kl = tid >> 2, q = tid & 3;
        float p = 0.f;
        #pragma unroll
        for (int j = 0; j < 8; ++j) p += sm[kl][q*8 + j]*swsh[q*8 + j];
        p += __shfl_xor_sync(0xffffffffu, p, 1);
        p += __shfl_xor_sync(0xffffffffu, p, 2);
        if (q == 0 && k0 + kl < Hh)
            g_vpart[((size_t)lr_*10 + ny)*Hh + k0 + kl] = p;
    }
}

__device__ void d_gather(const void* __restrict__ tags, int idx) {
    const int N0 = Bb*Ss*XKW;
    if (idx < N0) {
        int kw = idx % XKW, bs = idx / XKW;
        if (kw < Hh/2) {
            int tg = load_tag(tags, bs);
            g_xbf[idx] = packbf(g_T[tg*Hh + 2*kw], g_T[tg*Hh + 2*kw + 1]);
        } else {
            g_xbf[idx] = 0u;
        }
    } else if (idx < N0 + 64*XKW) {
        int j = idx - N0;
        int kw = j % XKW, p = j / XKW;
        g_tbf[j] = (p < NPOS && kw < Hh/2)
                 ? packbf(g_T[p*Hh + 2*kw], g_T[p*Hh + 2*kw + 1]) : 0u;
    }
}

__device__ void d_vsum(int i) {
    if (i >= 2*48*XKW) return;
    int kw = i % XKW, lr2 = i / XKW;
    int l = lr2 / 48, r = lr2 % 48;
    float lo = 0.f, hi = 0.f;
    if (r < Rr && kw < Hh/2) {
        int lr_ = l*Rr + r;
        #pragma unroll
        for (int ny = 0; ny < 10; ++ny) {
            const float* vp = g_vpart + ((size_t)lr_*10 + ny)*Hh;
            lo += vp[2*kw]; hi += vp[2*kw + 1];
        }
    }
    g_vbf[i] = packbf(lo, hi);
}

// ---------------------------------------------------------------------------
// TH[r] = T @ W_r (tid < 128)
__device__ void d_thgemm(int oc, int r) {
    int tid = threadIdx.x, wid = tid >> 5, lane = tid & 31;
    int lq = lane >> 2, lr = lane & 3;
    int mw = wid >> 1, nw = wid & 1;

    extern __shared__ uint32_t smu[];
    uint32_t sm_sh = (uint32_t)__cvta_generic_to_shared(smu);
    const uint32_t wsOff = 64*KW*4;

    const uint32_t* wg = g_wbf + ((size_t)r*WNP + oc*104)*XKW;

    uint32_t aOff = (((mw*32 + (lane & 15))*KW + (lane >> 4)*4) << 2);
    int rw = lane & 7, grp = lane >> 3;
    uint32_t bRow = (grp >> 1)*8 + rw;
    uint32_t bWof = (grp & 1)*4;
    uint32_t rw2 = lane & 7, bW2 = ((lane >> 3) & 1)*4;
    int nBase = nw ? 56 : 0;

    float acc[2][7][4];
    #pragma unroll
    for (int t = 0; t < 2; ++t)
        #pragma unroll
        for (int j = 0; j < 7; ++j)
            #pragma unroll
            for (int q = 0; q < 4; ++q) acc[t][j][q] = 0.f;

    auto stage = [&](int kc, int bsel) {
        uint32_t base = sm_sh + bsel*(TBUF*4);
        #pragma unroll 1
        for (int i = tid; i < 1344; i += 128) {
            int row = i >> 3, q = i & 7;
            if (row < 64) {
                cpa16(base + ((row*KW + q*4) << 2), g_tbf + row*XKW + kc*32 + q*4);
            } else {
                int n = row - 64;
                cpa16(base + wsOff + ((n*KW + q*4) << 2),
                      wg + (size_t)n*XKW + kc*32 + q*4);
            }
        }
        CP_COMMIT();
    };

    stage(0, 0);
    for (int kc = 0; kc < 5; ++kc) {
        int bsel = kc & 1;
        if (kc < 4) { stage(kc + 1, bsel ^ 1); CP_WAIT(1); }
        else        { CP_WAIT(0); }
        __syncthreads();
        uint32_t base = sm_sh + bsel*(TBUF*4);
        #pragma unroll
        for (int ks = 0; ks < 4; ++ks) {
            uint32_t A[2][4];
            #pragma unroll
            for (int t = 0; t < 2; ++t)
                LDSM4(A[t][0], A[t][1], A[t][2], A[t][3],
                      base + aOff + (uint32_t)t*(16*KW*4) + ks*32);
            #pragma unroll
            for (int p = 0; p < 3; ++p) {
                uint32_t b0, b1, b2, b3;
                LDSM4(b0, b1, b2, b3,
                      base + wsOff + ((((nBase + p*16 + bRow)*KW + bWof) << 2) + ks*32));
                #pragma unroll
                for (int t = 0; t < 2; ++t) {
                    MMA_BF16(acc[t][2*p],   A[t][0],A[t][1],A[t][2],A[t][3], b0, b1);
                    MMA_BF16(acc[t][2*p+1], A[t][0],A[t][1],A[t][2],A[t][3], b2, b3);
                }
            }
            if (nw == 0) {
                uint32_t c0, c1;
                LDSM2(c0, c1, base + wsOff + ((((48 + rw2)*KW + bW2) << 2) + ks*32));
                #pragma unroll
                for (int t = 0; t < 2; ++t)
                    MMA_BF16(acc[t][6], A[t][0],A[t][1],A[t][2],A[t][3], c0, c1);
            }
        }
        __syncthreads();
    }
    int nt0 = nw*7, nts = nw ? 6 : 7;
    #pragma unroll
    for (int t = 0; t < 2; ++t) {
        int row = mw*32 + t*16 + lq;
        #pragma unroll
        for (int j = 0; j < 7; ++j) {
            if (j < nts) {
                int c = (nt0 + j)*8 + lr*2;
                size_t b0i = ((size_t)r*WNP + oc*104 + c)*64;
                size_t b1i = ((size_t)r*WNP + oc*104 + c + 1)*64;
                g_tht[b0i + row]     = (unsigned short)packbf(acc[t][j][0], 0.f);
                g_tht[b1i + row]     = (unsigned short)packbf(acc[t][j][1], 0.f);
                g_tht[b0i + row + 8] = (unsigned short)packbf(acc[t][j][2], 0.f);
                g_tht[b1i + row + 8] = (unsigned short)packbf(acc[t][j][3], 0.f);
            }
        }
    }
}

// ---------------------------------------------------------------------------
__device__ void d_ugemm(int l, int bp) {
    int tid = threadIdx.x, wid = tid >> 5, lane = tid & 31;
    int lq = lane >> 2, lr = lane & 3;
    int mw = wid >> 1, nw = wid & 1;

    extern __shared__ uint32_t smu[];
    uint32_t sm_sh = (uint32_t)__cvta_generic_to_shared(smu);
    const uint32_t vOff = 192*KW*4;

    const uint32_t* xg = g_xbf + (size_t)(bp*192)*XKW;
    const uint32_t* vg = g_vbf + (size_t)(l*48)*XKW;

    uint32_t aOff = (((mw*48 + (lane & 15))*KW + (lane >> 4)*4) << 2);
    int rw = lane & 7, grp = lane >> 3;
    uint32_t bRow = (grp >> 1)*8 + rw;
    uint32_t bWof = (grp & 1)*4;
    uint32_t rw2 = lane & 7, bW2 = ((lane >> 3) & 1)*4;
    int nBase = nw*24;

    float acc[3][3][4];
    #pragma unroll
    for (int t = 0; t < 3; ++t)
        #pragma unroll
        for (int j = 0; j < 3; ++j)
            #pragma unroll
            for (int q = 0; q < 4; ++q) acc[t][j][q] = 0.f;

    auto stage = [&](int kc, int bsel) {
        uint32_t base = sm_sh + bsel*(UBUF*4);
        #pragma unroll 1
        for (int i = tid; i < 1920; i += 256) {
            uint32_t dst; const uint32_t* src;
            int row = i >> 3, q = i & 7;
            if (row < 192) {
                dst = base + ((row*KW + q*4) << 2);
                src = xg + (size_t)row*XKW + kc*32 + q*4;
            } else {
                int vr = row - 192;
                dst = base + vOff + ((vr*KW + q*4) << 2);
                src = vg + (size_t)vr*XKW + kc*32 + q*4;
            }
            cpa16(dst, src);
        }
        CP_COMMIT();
    };

    stage(0, 0);
    for (int kc = 0; kc < 5; ++kc) {
        int bsel = kc & 1;
        if (kc < 4) { stage(kc + 1, bsel ^ 1); CP_WAIT(1); }
        else        { CP_WAIT(0); }
        __syncthreads();
        uint32_t base = sm_sh + bsel*(UBUF*4);
        #pragma unroll
        for (int ks = 0; ks < 4; ++ks) {
            uint32_t A[3][4];
            #pragma unroll
            for (int t = 0; t < 3; ++t)
                LDSM4(A[t][0], A[t][1], A[t][2], A[t][3],
                      base + aOff + (uint32_t)t*(16*KW*4) + ks*32);
            uint32_t b0, b1, b2, b3;
            LDSM4(b0, b1, b2, b3,
                  base + vOff + ((((nBase + bRow)*KW + bWof) << 2) + ks*32));
            uint32_t c0, c1;
            LDSM2(c0, c1, base + vOff + ((((nBase + 16 + rw2)*KW + bW2) << 2) + ks*32));
            #pragma unroll
            for (int t = 0; t < 3; ++t) {
                MMA_BF16(acc[t][0], A[t][0],A[t][1],A[t][2],A[t][3], b0, b1);
                MMA_BF16(acc[t][1], A[t][0],A[t][1],A[t][2],A[t][3], b2, b3);
                MMA_BF16(acc[t][2], A[t][0],A[t][1],A[t][2],A[t][3], c0, c1);
            }
        }
        __syncthreads();
    }
    #pragma unroll
    for (int t = 0; t < 3; ++t) {
        int row0 = mw*48 + t*16 + lq;
        #pragma unroll
        for (int j = 0; j < 3; ++j) {
            int c = nBase + j*8 + lr*2;
            #pragma unroll
            for (int h = 0; h < 2; ++h) {
                int row = row0 + h*8;
                int b = bp*2 + (row >= 96), s = row & 95;
                if (c < Rr)     g_u[(b*Rr + c)*Ss + s]     = acc[t][j][2*h];
                if (c + 1 < Rr) g_u[(b*Rr + c + 1)*Ss + s] = acc[t][j][2*h + 1];
            }
        }
    }
}

// ---------------------------------------------------------------------------
// scores[b,r,s] = (adj_br @ u)[s]/denom_safe — grid (r, b), 96 threads
__global__ void k_scores(const float* __restrict__ adj) {
    int r = blockIdx.x, b = blockIdx.y;
    __shared__ float u[Ss];
    int t = threadIdx.x;  // 96
    u[t] = g_u[(b*Rr + r)*Ss + t];
    __syncthreads();
    const float4* ar = (const float4*)(adj + (((size_t)b*Rr + r)*Ss + t)*Ss);
    float d = 0.f, sr = 0.f;
    #pragma unroll 6
    for (int j = 0; j < Ss/4; ++j) {
        float4 av = ar[j];
        d  += av.x + av.y + av.z + av.w;
        sr += av.x*u[4*j] + av.y*u[4*j+1] + av.z*u[4*j+2] + av.w*u[4*j+3];
    }
    float ds = (d == 0.f) ? 1.f : d;
    int o = (b*Rr + r)*Ss + t;
    g_sc[o]  = sr/ds;
    g_den[o] = ds;
}

// ---------------------------------------------------------------------------
// Softmax (inline, per block) + weighted-adj emit.  Grid (b, r), 128 threads.
// l=0: Ac[s][p] = w[s] * segmented adj sums (tag-compressed)
// l=1: A'[s][t] = w[s] * adj[s][t]
__global__ void __launch_bounds__(128)
k_awb(const float* __restrict__ adj, int l) {
    int b = blockIdx.x, r = blockIdx.y;
    __shared__ float wdS[96];
    __shared__ float adjsm[96][97];
    __shared__ unsigned short permS[96];
    __shared__ unsigned short segsS[65];
    int tid = threadIdx.x;
    if (tid < 96) {
        int s = tid;
        float mx = -1e30f;
        for (int rr = 0; rr < Rr; ++rr) mx = fmaxf(mx, g_sc[(b*Rr + rr)*Ss + s]);
        float Z = 0.f;
        for (int rr = 0; rr < Rr; ++rr) Z += expf(g_sc[(b*Rr + rr)*Ss + s] - mx);
        int o = (b*Rr + r)*Ss + s;
        wdS[s] = expf(g_sc[o] - mx) / (Z * g_den[o]);
    }
    const float4* ar = (const float4*)(adj + ((size_t)b*Rr + r)*Ss*Ss);
    if (l == 0) {
        if (tid < 96) permS[tid] = g_perm[b][tid];
        if (tid < 65) segsS[tid] = g_segs[b][tid];
        #pragma unroll 4
        for (int i = tid; i < 96*24; i += 128) {
            int s = i / 24, q = i % 24;
            float4 v = ar[i];
            adjsm[s][q*4]   = v.x; adjsm[s][q*4+1] = v.y;
            adjsm[s][q*4+2] = v.z; adjsm[s][q*4+3] = v.w;
        }
        __syncthreads();
        uint32_t* out = g_acbf + ((size_t)(b*Rr + r))*Ss*32;
        #pragma unroll 4
        for (int i = tid; i < 96*32; i += 128) {
            int s = i >> 5, p2 = i & 31;
            float w = wdS[s];
            int p0 = 2*p2;
            float a0 = 0.f, a1 = 0.f;
            for (int j = segsS[p0]; j < segsS[p0+1]; ++j) a0 += adjsm[s][permS[j]];
            for (int j = segsS[p0+1]; j < segsS[p0+2]; ++j) a1 += adjsm[s][permS[j]];
            out[s*32 + p2] = packbf(a0*w, a1*w);
        }
    } else {
        __syncthreads();
        uint32_t* out = g_apbf + ((size_t)(b*Rr + r))*Ss*48;
        #pragma unroll 4
        for (int i = tid; i < 96*24; i += 128) {
            int s = i / 24, q = i % 24;
            float4 av = ar[i];
            float w = wdS[s];
            out[s*48 + 2*q]     = packbf(av.x*w, av.y*w);
            out[s*48 + 2*q + 1] = packbf(av.z*w, av.w*w);
        }
    }
}

// ---------------------------------------------------------------------------
__device__ void d_hidgemm(int l, int bp, int oc, int r) {
    int tid = threadIdx.x, wid = tid >> 5, lane = tid & 31;
    int lq = lane >> 2, lr = lane & 3;
    int mw = wid >> 1, nw = wid & 1;

    extern __shared__ uint32_t smu[];
    uint32_t sm_sh = (uint32_t)__cvta_generic_to_shared(smu);

    const uint32_t* xg = g_xbf + (size_t)(bp*2)*Ss*XKW;
    const uint32_t* wg = g_wbf + ((size_t)(l*Rr + r)*WNP + oc*OCW)*XKW;

    const uint32_t wsOff = 192*KW*4;

    uint32_t aOff = (((mw*48 + (lane & 15))*KW + (lane >> 4)*4) << 2);
    int rw = lane & 7, grp = lane >> 3;
    uint32_t bRow = (grp >> 1)*8 + rw;
    uint32_t bWof = (grp & 1)*4;
    uint32_t rw2 = lane & 7, bW2 = ((lane >> 3) & 1)*4;
    int nBase = nw ? 56 : 0;

    float acc[3][7][4];
    #pragma unroll
    for (int t = 0; t < 3; ++t)
        #pragma unroll
        for (int j = 0; j < 7; ++j)
            #pragma unroll
            for (int q = 0; q < 4; ++q) acc[t][j][q] = 0.f;

    auto stage = [&](int kc, int bsel) {
        uint32_t base = sm_sh + bsel*(ABUF2*4);
        #pragma unroll 1
        for (int i = tid; i < 2368; i += 256) {
            uint32_t dst; const uint32_t* src;
            if (i < 1536) {
                int row = i >> 3, q = i & 7;
                dst = base + ((row*KW + q*4) << 2);
                src = xg + row*XKW + kc*32 + q*4;
            } else {
                int j = i - 1536;
                int row = j >> 3, q = j & 7;
                dst = base + wsOff + ((row*KW + q*4) << 2);
                src = wg + (size_t)row*XKW + kc*32 + q*4;
            }
            cpa16(dst, src);
        }
        CP_COMMIT();
    };

    stage(0, 0);
    for (int kc = 0; kc < 5; ++kc) {
        int bsel = kc & 1;
        if (kc < 4) { stage(kc + 1, bsel ^ 1); CP_WAIT(1); }
        else        { CP_WAIT(0); }
        __syncthreads();
        uint32_t base = sm_sh + bsel*(ABUF2*4);
        #pragma unroll
        for (int ks = 0; ks < 4; ++ks) {
            uint32_t A[3][4];
            #pragma unroll
            for (int t = 0; t < 3; ++t)
                LDSM4(A[t][0], A[t][1], A[t][2], A[t][3],
                      base + aOff + (uint32_t)t*(16*KW*4) + ks*32);
            #pragma unroll
            for (int p = 0; p < 3; ++p) {
                uint32_t b0, b1, b2, b3;
                LDSM4(b0, b1, b2, b3,
                      base + wsOff + ((((nBase + p*16 + bRow)*KW + bWof) << 2) + ks*32));
                #pragma unroll
                for (int t = 0; t < 3; ++t) {
                    MMA_BF16(acc[t][2*p],   A[t][0],A[t][1],A[t][2],A[t][3], b0, b1);
                    MMA_BF16(acc[t][2*p+1], A[t][0],A[t][1],A[t][2],A[t][3], b2, b3);
                }
            }
            if (nw == 0) {
                uint32_t c0, c1;
                LDSM2(c0, c1, base + wsOff + ((((48 + rw2)*KW + bW2) << 2) + ks*32));
                #pragma unroll
                for (int t = 0; t < 3; ++t)
                    MMA_BF16(acc[t][6], A[t][0],A[t][1],A[t][2],A[t][3], c0, c1);
            }
        }
        __syncthreads();
    }
    {
        int b_local = mw >> 1;
        int rloc = mw*48 - b_local*96;
        __nv_bfloat16* hidB = (__nv_bfloat16*)(smu + b_local*ABUF2);
        int nt0 = nw*7, nts = nw ? 6 : 7;
        #pragma unroll
        for (int t = 0; t < 3; ++t) {
            int row = rloc + t*16 + lq;
            #pragma unroll
            for (int j = 0; j < 7; ++j) {
                if (j < nts) {
                    int c = (nt0 + j)*8 + lr*2;
                    hidB[(size_t)c*(2*TW) + row]         = __float2bfloat16_rn(acc[t][j][0]);
                    hidB[(size_t)(c+1)*(2*TW) + row]     = __float2bfloat16_rn(acc[t][j][1]);
                    hidB[(size_t)c*(2*TW) + row + 8]     = __float2bfloat16_rn(acc[t][j][2]);
                    hidB[(size_t)(c+1)*(2*TW) + row + 8] = __float2bfloat16_rn(acc[t][j][3]);
                }
            }
        }
    }
    __syncthreads();
    #pragma unroll
    for (int bi = 0; bi < 2; ++bi) {
        uint32_t* hg = g_hid + ((size_t)(r*Bb + bp*2 + bi)*3 + oc)*HCH;
        const uint32_t* src = smu + bi*ABUF2;
        #pragma unroll 4
        for (int i = tid; i < HCH; i += 256) hg[i] = src[i];
    }
}

// ---------------------------------------------------------------------------
// Merged launch kernels
__global__ void __launch_bounds__(320)
k_pre1(const float* __restrict__ posemb, const float* __restrict__ linW,
       const float* __restrict__ linb, const float* __restrict__ text,
       const float* __restrict__ rgcnW, const float* __restrict__ scoreW,
       const void* tags, const void* masks, int ntag, int nmask) {
    int bx = blockIdx.x;
    if (bx < 4100) {
        if (threadIdx.x >= 256) return;
        d_wcvt(rgcnW, scoreW, bx % 82, (bx/82) % 10, bx/820);
    } else {
        d_detpost(posemb, linW, linb, text, tags, masks, ntag, nmask, bx - 4100);
    }
}

__global__ void k_pre2(const void* tags) {
    int bx = blockIdx.x;
    if (bx < 1960) d_gather(tags, bx*256 + threadIdx.x);
    else           d_vsum((bx - 1960)*256 + threadIdx.x);
}

__global__ void __launch_bounds__(256)
k_pre3() {
    int bx = blockIdx.x;
    if (bx < 123) {
        if (threadIdx.x >= 128) return;
        d_thgemm(bx % 3, bx / 3);
    } else {
        d_ugemm(0, bx - 123);
    }
}

__global__ void __launch_bounds__(256, 2)
k_l1a() {
    int bx = blockIdx.x;
    if (bx < 1968) d_hidgemm(1, bx % 16, (bx/16) % 3, bx/48);
    else           d_ugemm(1, bx - 1968);
}

// ---------------------------------------------------------------------------
// GEMM B dual-mode:
//  l=1: part += A'(96xK96) @ hid(104xK96)   (strides TW)
//  l=0: part += Ac(96xK64) @ TH(104xK64)    (strides KW), TH shared across b
__global__ void __launch_bounds__(192)
k_pass2b(int l) {
    int b = blockIdx.x, oc = blockIdx.y, g = blockIdx.z;
    int tid = threadIdx.x, wid = tid >> 5, lane = tid & 31;
    int lq = lane >> 2, lr = lane & 3;
    int mw = wid % 3, nw = wid / 3;
    int r0 = g*14, nr = (g == 2) ? 13 : 14;

    extern __shared__ uint32_t smu[];
    uint32_t sm_sh = (uint32_t)__cvta_generic_to_shared(smu);

    const int AST = l ? TW : KW;
    const uint32_t bReg = l ? (96*TW*4) : (96*KW*4);
    const int KS = l ? 6 : 4;

    uint32_t aOff = (((mw*32 + (lane & 15))*AST + (lane >> 4)*4) << 2);
    int rw = lane & 7, grp = lane >> 3;
    uint32_t bRow = (grp >> 1)*8 + rw;
    uint32_t bWof = (grp & 1)*4;
    uint32_t rw2 = lane & 7, bW2 = ((lane >> 3) & 1)*4;
    int nBase = nw ? 56 : 0;

    float acc[2][7][4];
    #pragma unroll
    for (int t = 0; t < 2; ++t)
        #pragma unroll
        for (int j = 0; j < 7; ++j)
            #pragma unroll
            for (int q = 0; q < 4; ++q) acc[t][j][q] = 0.f;

    auto stage = [&](int rr, int bsel) {
        int r = r0 + rr;
        uint32_t base = sm_sh + bsel*(BBUF*4);
        if (l) {
            const uint32_t* ag = g_apbf + ((size_t)(b*Rr + r))*Ss*48;
            const uint32_t* hg = g_hid + ((size_t)(r*Bb + b)*3 + oc)*HCH;
            #pragma unroll 1
            for (int i = tid; i < 2504; i += 192) {
                uint32_t dst; const uint32_t* src;
                if (i < 1152) {
                    int row = i / 12, q = i % 12;
                    dst = base + ((row*TW + q*4) << 2);
                    src = ag + row*48 + q*4;
                } else {
                    int j = i - 1152;
                    dst = base + bReg + (j << 4);
                    src = hg + j*4;
                }
                cpa16(dst, src);
            }
        } else {
            const uint32_t* ag = g_acbf + ((size_t)(b*Rr + r))*Ss*32;
            const uint32_t* tg = (const uint32_t*)(g_tht + ((size_t)r*WNP + oc*OCW)*64);
            #pragma unroll 1
            for (int i = tid; i < 1600; i += 192) {
                uint32_t dst; const uint32_t* src;
                if (i < 768) {
                    int row = i >> 3, q = i & 7;
                    dst = base + ((row*KW + q*4) << 2);
                    src = ag + row*32 + q*4;
                } else {
                    int j = i - 768;
                    int row = j >> 3, q = j & 7;
                    dst = base + bReg + ((row*KW + q*4) << 2);
                    src = tg + row*32 + q*4;
                }
                cpa16(dst, src);
            }
        }
        CP_COMMIT();
    };

    stage(0, 0);
    for (int rr = 0; rr < nr; ++rr) {
        int bsel = rr & 1;
        if (rr + 1 < nr) { stage(rr + 1, bsel ^ 1); CP_WAIT(1); }
        else             { CP_WAIT(0); }
        __syncthreads();
        uint32_t base = sm_sh + bsel*(BBUF*4);
        #pragma unroll 2
        for (int ks = 0; ks < KS; ++ks) {
            uint32_t A[2][4];
            #pragma unroll
            for (int t = 0; t < 2; ++t)
                LDSM4(A[t][0], A[t][1], A[t][2], A[t][3],
                      base + aOff + (uint32_t)t*(16*AST*4) + ks*32);
            #pragma unroll
            for (int p = 0; p < 3; ++p) {
                uint32_t b0, b1, b2, b3;
                LDSM4(b0, b1, b2, b3,
                      base + bReg + ((((nBase + p*16 + bRow)*AST + bWof) << 2) + ks*32));
                #pragma unroll
                for (int t = 0; t < 2; ++t) {
                    MMA_BF16(acc[t][2*p],   A[t][0],A[t][1],A[t][2],A[t][3], b0, b1);
                    MMA_BF16(acc[t][2*p+1], A[t][0],A[t][1],A[t][2],A[t][3], b2, b3);
                }
            }
            if (nw == 0) {
                uint32_t c0, c1;
                LDSM2(c0, c1, base + bReg + ((((48 + rw2)*AST + bW2) << 2) + ks*32));
                #pragma unroll
                for (int t = 0; t < 2; ++t)
                    MMA_BF16(acc[t][6], A[t][0],A[t][1],A[t][2],A[t][3], c0, c1);
            }
        }
        __syncthreads();
    }

    float* pp = g_part + ((size_t)(b*NG + g))*Ss*Hh;
    int o0 = oc*OCW;
    int nt0 = nw*7, nts = nw ? 6 : 7;
    #pragma unroll
    for (int t = 0; t < 2; ++t) {
        int row = mw*32 + t*16 + lq;
        #pragma unroll
        for (int j = 0; j < 7; ++j) {
            if (j < nts) {
                int c = (nt0 + j)*8 + lr*2;
                if (c < OCW) {
                    pp[row*Hh + o0 + c]         = acc[t][j][0];
                    pp[row*Hh + o0 + c + 1]     = acc[t][j][1];
                    pp[(row+8)*Hh + o0 + c]     = acc[t][j][2];
                    pp[(row+8)*Hh + o0 + c + 1] = acc[t][j][3];
                }
            }
        }
    }
}

// x_out = relu(sum over groups): l=0 -> packed bf16x2; l=1 -> fp32 for pooling
__global__ void k_reduce(int l) {
    int idx = blockIdx.x*blockDim.x + threadIdx.x;
    if (l == 0) {
        if (idx >= Bb*Ss*XKW) return;
        int kw = idx % XKW, bs = idx / XKW;
        if (kw >= Hh/2) return;
        int b = bs / Ss;
        size_t inner = (size_t)(bs % Ss)*Hh + 2*kw;
        float a0 = 0.f, a1 = 0.f;
        #pragma unroll
        for (int g = 0; g < NG; ++g) {
            const float* pp = g_part + ((size_t)(b*NG + g))*Ss*Hh + inner;
            a0 += pp[0]; a1 += pp[1];
        }
        g_xbf[idx] = packbf(fmaxf(a0, 0.f), fmaxf(a1, 0.f));
    } else {
        if (idx >= Bb*Ss*(Hh/2)) return;
        int kw = idx % (Hh/2), bs = idx / (Hh/2);
        int b = bs / Ss;
        size_t inner = (size_t)(bs % Ss)*Hh + 2*kw;
        float a0 = 0.f, a1 = 0.f;
        #pragma unroll
        for (int g = 0; g < NG; ++g) {
            const float* pp = g_part + ((size_t)(b*NG + g))*Ss*Hh + inner;
            a0 += pp[0]; a1 += pp[1];
        }
        *(float2*)&g_x0[(size_t)bs*Hh + 2*kw] =
            make_float2(fmaxf(a0, 0.f), fmaxf(a1, 0.f));
    }
}

// ---------------------------------------------------------------------------
__global__ void k_final(const float* __restrict__ dW, const float* __restrict__ db,
                        float* __restrict__ out) {
    int b = blockIdx.x, tid = threadIdx.x;  // 320
    __shared__ float red0[320], red1[320], red2[320];
    float p0 = 0.f, p1 = 0.f, p2 = 0.f;
    if (tid < Hh) {
        float a = 0.f;
        for (int s = 0; s < Ss; ++s) a += g_x0[((size_t)b*Ss + s)*Hh + tid];
        float hg = a / g_rlen[b];
        float hc = g_hcmean[b*Hh + tid];
        p0 = hg*dW[tid*NLAB + 0] + hc*dW[(Hh + tid)*NLAB + 0];
        p1 = hg*dW[tid*NLAB + 1] + hc*dW[(Hh + tid)*NLAB + 1];
        p2 = hg*dW[tid*NLAB + 2] + hc*dW[(Hh + tid)*NLAB + 2];
    }
    red0[tid] = p0; red1[tid] = p1; red2[tid] = p2;
    __syncthreads();
    for (int st = 160; st >= 5; st >>= 1) {
        if (tid < st) {
            red0[tid] += red0[tid + st];
            red1[tid] += red1[tid + st];
            red2[tid] += red2[tid + st];
        }
        __syncthreads();
    }
    if (tid < NLAB) {
        float* rn = (tid == 0) ? red0 : (tid == 1) ? red1 : red2;
        float a = db[tid];
        #pragma unroll
        for (int i = 0; i < 5; ++i) a += rn[i];
        out[b*NLAB + tid] = a;
    }
}

// ---------------------------------------------------------------------------
extern "C" void kernel_launch(void* const* d_in, const int* in_sizes, int n_in,
                              void* d_out, int out_size) {
    const float* text   = (const float*)d_in[0];
    const void*  masks  = d_in[1];
    const void*  tags   = d_in[2];
    const float* adj    = (const float*)d_in[3];
    const float* posemb = (const float*)d_in[4];
    const float* linW   = (const float*)d_in[5];
    const float* linb   = (const float*)d_in[6];
    const float* rgcnW  = (const float*)d_in[7];
    const float* scoreW = (const float*)d_in[8];
    // d_in[9] = score_b: softmax over relations is invariant to it — unused
    const float* dW     = (const float*)d_in[10];
    const float* db     = (const float*)d_in[11];
    float*       out    = (float*)d_out;

    const int SMEM_P3 = 2*UBUF*4;    // 69120
    const int SMEM_L1 = 2*ABUF2*4;   // 85248
    const int SMEM_B  = 2*BBUF*4;    // 83200
    cudaFuncSetAttribute(k_pre3,  cudaFuncAttributeMaxDynamicSharedMemorySize, SMEM_P3);
    cudaFuncSetAttribute(k_l1a,   cudaFuncAttributeMaxDynamicSharedMemorySize, SMEM_L1);
    cudaFuncSetAttribute(k_pass2b, cudaFuncAttributeMaxDynamicSharedMemorySize, SMEM_B);

    k_pre1<<<4100 + NPOS + 2 + Bb, 320>>>(posemb, linW, linb, text, rgcnW, scoreW,
                                          tags, masks, in_sizes[2], in_sizes[1]);
    k_pre2<<<1960 + 60, 256>>>(tags);
    k_pre3<<<123 + 16, 256, SMEM_P3>>>();
    k_scores<<<dim3(Rr, Bb), Ss>>>(adj);            // ncu capture slot (idx 3)
    k_awb<<<dim3(Bb, Rr), 128>>>(adj, 0);
    k_pass2b<<<dim3(Bb, 3, NG), 192, SMEM_B>>>(0);
    k_reduce<<<(Bb*Ss*XKW + 255)/256, 256>>>(0);
    k_l1a<<<1968 + 16, 256, SMEM_L1>>>();
    k_scores<<<dim3(Rr, Bb), Ss>>>(adj);
    k_awb<<<dim3(Bb, Rr), 128>>>(adj, 1);
    k_pass2b<<<dim3(Bb, 3, NG), 192, SMEM_B>>>(1);
    k_reduce<<<(Bb*Ss*XKW + 255)/256, 256>>>(1);
    k_final<<<Bb, 320>>>(dW, db, out);
}